// round 12
// baseline (speedup 1.0000x reference)
#include <cuda_runtime.h>
#include <math.h>
#include <stdint.h>

#define DD 200
#define NTY 4
#define NET 38
#define NT1 39
#define BB 256
#define LL 1024
#define EE 262144
#define NN 51200
#define NCOMBO 608
#define TOTROWS (EE + NN)

// f32x2 packed-math helpers
#define FMA2(d,a,b)  asm("fma.rn.f32x2 %0, %1, %2, %3;" : "=l"(d) : "l"(a), "l"(b), "l"(d))
#define PACK2(d,x,y) asm("mov.b64 %0, {%1, %2};" : "=l"(d) : "f"(x), "f"(y))
#define UNPACK2(x,y,d) asm("mov.b64 {%0, %1}, %2;" : "=f"(x), "=f"(y) : "l"(d))

#define CVT_TF32(u,f) asm("cvt.rna.tf32.f32 %0, %1;" : "=r"(u) : "f"(f))
#define MMA_TF32(c0,c1,c2,c3,a0,a1,a2,a3,b0,b1) \
  asm("mma.sync.aligned.m16n8k8.row.col.f32.tf32.tf32.f32 " \
      "{%0,%1,%2,%3},{%4,%5,%6,%7},{%8,%9},{%0,%1,%2,%3};" \
      : "+f"(c0),"+f"(c1),"+f"(c2),"+f"(c3) \
      : "r"(a0),"r"(a1),"r"(a2),"r"(a3),"r"(b0),"r"(b1))

// ------------------------- scratch -------------------------
__device__ float d_coeff[(size_t)NN * NT1];
__device__ float d_sums[NT1 * DD];
__device__ int   d_cntT[NT1];
__device__ int   d_cntE[NCOMBO];
__device__ int   d_cntN[NTY];
__device__ int   d_combo[EE];
__device__ int   d_cntSrc[NN];
__device__ int   d_dstCnt[NN];
__device__ int   d_dstOff[NN + 1];
__device__ int   d_srcOff[NN + 1];
__device__ int   d_cursorD[NN];
__device__ int   d_cursorS[NN];
__device__ int   d_csr[TOTROWS];
__device__ int   d_csrS[TOTROWS];
__device__ int   d_blkSum[2][50];
__device__ float d_meanT[NT1 * DD];
__device__ float d_preE[NCOMBO * DD];
__device__ float d_preS[NTY * DD];
__device__ float d_embE[NCOMBO * DD];
__device__ float d_embS[NTY * DD];
__device__ float d_h2[NCOMBO * DD];
__device__ float d_Rtab[NCOMBO * DD];
__device__ float d_bn1m[DD], d_bn1r[DD], d_bn2m[DD], d_bn2r[DD], d_bn3m[DD], d_bn3r[DD];
__device__ float d_upd[BB * DD];
__device__ float d_UKall[(BB + NTY) * DD];
__device__ float d_UMall[(BB + NTY) * DD];
__device__ float d_Wcat[DD * 640];
__device__ float d_bcat[640];
__device__ float d_Wo1P[DD * 256];
__device__ float d_Wo2P[DD * 256];
__device__ float d_XKMQ[(size_t)NN * 600];    // per-node [XK+bk | XM+bm | (XQ+bq)*invs]
__device__ float d_ex[(size_t)TOTROWS * 4];
__device__ float d_den[NN * 4];
__device__ float d_aggr[(size_t)NN * DD];
__device__ float d_Y1[(size_t)NN * DD];
__device__ float d_colsum[DD], d_colsum2[DD];

// ------------------------- zero init + node hist (fused) -------------------------
__global__ void k_zero(const int* __restrict__ ntp) {
    long long i0 = (long long)blockIdx.x * blockDim.x + threadIdx.x;
    long long st = (long long)gridDim.x * blockDim.x;
    for (long long i = i0; i < (long long)NT1 * NN; i += st) d_coeff[i] = 0.f;
    for (long long i = i0; i < NT1 * DD; i += st) d_sums[i] = 0.f;
    for (long long i = i0; i < NCOMBO; i += st) d_cntE[i] = 0;
    for (long long i = i0; i < NT1; i += st) d_cntT[i] = 0;
    for (long long i = i0; i < NTY; i += st) d_cntN[i] = 0;
    for (long long i = i0; i < DD; i += st) { d_colsum[i] = 0.f; d_colsum2[i] = 0.f; }
    for (long long i = i0; i < NN; i += st) {
        d_cntSrc[i] = 1;
        d_dstCnt[i] = 1;
        atomicAdd(&d_cntN[ntp[i]], 1);
    }
}

// smem histograms + 4 edges/thread for atomic-chain ILP
__global__ void k_edgehist(const int* __restrict__ ei, const int* __restrict__ et,
                           const int* __restrict__ ntp) {
    __shared__ int sT[NT1];
    __shared__ int sE[NCOMBO];
    int tid = threadIdx.x;
    for (int i = tid; i < NT1; i += 256) sT[i] = 0;
    for (int i = tid; i < NCOMBO; i += 256) sE[i] = 0;
    __syncthreads();
    int e0 = blockIdx.x * 1024 + tid;
    int s[4], dd[4], t[4];
#pragma unroll
    for (int j = 0; j < 4; j++) {
        int e = e0 + j * 256;
        s[j]  = ei[e];
        dd[j] = ei[EE + e];
        t[j]  = et[e];
    }
#pragma unroll
    for (int j = 0; j < 4; j++)
        atomicAdd(&d_coeff[(size_t)dd[j] * NT1 + t[j]], 1.f);
#pragma unroll
    for (int j = 0; j < 4; j++)
        atomicAdd(&d_coeff[(size_t)s[j] * NT1 + t[j]], -1.f);
#pragma unroll
    for (int j = 0; j < 4; j++) {
        int e = e0 + j * 256;
        atomicAdd(&sT[t[j]], 1);
        int c = (t[j] << 4) | (ntp[s[j]] << 2) | ntp[dd[j]];
        d_combo[e] = c;
        atomicAdd(&sE[c], 1);
    }
#pragma unroll
    for (int j = 0; j < 4; j++) atomicAdd(&d_cntSrc[s[j]], 1);
#pragma unroll
    for (int j = 0; j < 4; j++) atomicAdd(&d_dstCnt[dd[j]], 1);
    __syncthreads();
    for (int i = tid; i < NT1; i += 256) if (sT[i]) atomicAdd(&d_cntT[i], sT[i]);
    for (int i = tid; i < NCOMBO; i += 256) if (sE[i]) atomicAdd(&d_cntE[i], sE[i]);
}

// ------------------------- dual CSR build (dst + src), 3-phase scan -------------------------
__global__ void k_scanA2() {                 // grid (50,2)
    __shared__ int sm[1024];
    int tid = threadIdx.x;
    const int* cnt = blockIdx.y ? d_cntSrc : d_dstCnt;
    sm[tid] = cnt[blockIdx.x * 1024 + tid];
    __syncthreads();
    for (int o = 512; o > 0; o >>= 1) {
        if (tid < o) sm[tid] += sm[tid + o];
        __syncthreads();
    }
    if (tid == 0) d_blkSum[blockIdx.y][blockIdx.x] = sm[0];
}

__global__ void k_scanB2() {                 // 2 blocks x 64
    __shared__ int sm[64];
    int y = blockIdx.x;
    int tid = threadIdx.x;
    int v = (tid < 50) ? d_blkSum[y][tid] : 0;
    sm[tid] = v;
    __syncthreads();
    for (int o = 1; o < 64; o <<= 1) {
        int t = (tid >= o) ? sm[tid - o] : 0;
        __syncthreads();
        sm[tid] += t;
        __syncthreads();
    }
    if (tid < 50) d_blkSum[y][tid] = sm[tid] - v;
    if (tid == 49) { if (y) d_srcOff[NN] = sm[49]; else d_dstOff[NN] = sm[49]; }
}

__global__ void k_scanC2() {                 // grid (50,2)
    __shared__ int sm[1024];
    int tid = threadIdx.x;
    int y = blockIdx.y;
    int g = blockIdx.x * 1024 + tid;
    int v = y ? d_cntSrc[g] : d_dstCnt[g];
    sm[tid] = v;
    __syncthreads();
    for (int o = 1; o < 1024; o <<= 1) {
        int t = (tid >= o) ? sm[tid - o] : 0;
        __syncthreads();
        sm[tid] += t;
        __syncthreads();
    }
    int excl = sm[tid] - v + d_blkSum[y][blockIdx.x];
    if (y) { d_srcOff[g] = excl; d_cursorS[g] = excl; }
    else   { d_dstOff[g] = excl; d_cursorD[g] = excl; }
}

__global__ void k_csrfill(const int* __restrict__ ei) {
    int i = blockIdx.x * blockDim.x + threadIdx.x;
    if (i >= TOTROWS) return;
    int dst = (i < EE) ? ei[EE + i] : (i - EE);
    d_csr[atomicAdd(&d_cursorD[dst], 1)] = i;
    int src = (i < EE) ? ei[i] : (i - EE);
    d_csrS[atomicAdd(&d_cursorS[src], 1)] = i;
}

// ------------------------- segment sums -------------------------
__global__ __launch_bounds__(128) void k_segsum3(const float* __restrict__ x) {
    __shared__ unsigned long long cf2[128][NT1];
    int tid = threadIdx.x;
    int n0 = blockIdx.x * 128;
    for (int i = tid; i < 128 * NT1; i += 128) {
        float c = d_coeff[(size_t)(n0 + i / NT1) * NT1 + (i % NT1)];
        unsigned long long c2; PACK2(c2, c, c);
        cf2[i / NT1][i % NT1] = c2;
    }
    __syncthreads();
    if (tid < 100) {
        unsigned long long acc[NT1];
#pragma unroll
        for (int t = 0; t < NT1; t++) acc[t] = 0ULL;
        for (int nn = 0; nn < 128; nn++) {
            float2 xv = *(const float2*)&x[(size_t)(n0 + nn) * DD + tid * 2];
            unsigned long long xv2; PACK2(xv2, xv.x, xv.y);
#pragma unroll
            for (int t = 0; t < NT1; t++)
                FMA2(acc[t], cf2[nn][t], xv2);
        }
#pragma unroll
        for (int t = 0; t < NT1; t++) {
            float lo, hi; UNPACK2(lo, hi, acc[t]);
            if (lo != 0.f) atomicAdd(&d_sums[t * DD + tid * 2], lo);
            if (hi != 0.f) atomicAdd(&d_sums[t * DD + tid * 2 + 1], hi);
        }
    }
}

__global__ void k_meanT() {
    int i = blockIdx.x * blockDim.x + threadIdx.x;
    if (i >= NT1 * DD) return;
    int t = i / DD;
    float c = (float)d_cntT[t];
    if (c < 1.f) c = 1.f;
    d_meanT[i] = d_sums[i] / c;
}

// ------------------------- combo tables -------------------------
__global__ void k_tables(const float* __restrict__ We1, const float* __restrict__ be1) {
    int c = blockIdx.x, d = threadIdx.x;
    if (d >= DD) return;
    if (c < NCOMBO) {
        int t = c >> 4, a = (c >> 2) & 3, b = c & 3;
        d_preE[c * DD + d] = We1[t * DD + d] + We1[(NT1 + a) * DD + d]
                           + We1[(NT1 + NTY + b) * DD + d] + be1[d];
    } else {
        int t = c - NCOMBO;
        d_preS[t * DD + d] = We1[NET * DD + d] + We1[(NT1 + t) * DD + d]
                           + We1[(NT1 + NTY + t) * DD + d] + be1[d];
    }
}

__global__ void k_bnstat1p() {
    int d = blockIdx.x, tid = threadIdx.x;
    __shared__ double rs[128], rs2[128];
    double s = 0.0, s2 = 0.0;
    for (int c = tid; c < NCOMBO; c += 128) {
        double w = (double)d_cntE[c], v = (double)d_preE[c * DD + d];
        s += w * v; s2 += w * v * v;
    }
    if (tid < NTY) {
        double w = (double)d_cntN[tid], v = (double)d_preS[tid * DD + d];
        s += w * v; s2 += w * v * v;
    }
    rs[tid] = s; rs2[tid] = s2;
    __syncthreads();
    for (int o = 64; o > 0; o >>= 1) {
        if (tid < o) { rs[tid] += rs[tid + o]; rs2[tid] += rs2[tid + o]; }
        __syncthreads();
    }
    if (tid == 0) {
        double m = rs[0] / (double)TOTROWS;
        double var = rs2[0] / (double)TOTROWS - m * m;
        d_bn1m[d] = (float)m;
        d_bn1r[d] = rsqrtf((float)var + 1e-5f);
    }
}

__global__ void k_emb(const float* __restrict__ We2, const float* __restrict__ be2,
                      const float* __restrict__ g, const float* __restrict__ bt) {
    int c = blockIdx.x, d = threadIdx.x;
    __shared__ float a[DD];
    const float* srow = (c < NCOMBO) ? &d_preE[c * DD] : &d_preS[(c - NCOMBO) * DD];
    if (d < DD) {
        float v = (srow[d] - d_bn1m[d]) * d_bn1r[d] * g[d] + bt[d];
        a[d] = fmaxf(v, 0.f);
    }
    __syncthreads();
    if (d < DD) {
        float acc = 0.f;
        for (int k = 0; k < DD; k++) acc += a[k] * We2[k * DD + d];
        float* dst = (c < NCOMBO) ? &d_embE[c * DD] : &d_embS[(c - NCOMBO) * DD];
        dst[d] = acc + be2[d];
    }
}

__global__ void k_h2pre(const float* __restrict__ Wa1, const float* __restrict__ ba1) {
    int c = blockIdx.x, d = threadIdx.x;
    __shared__ float e[DD], mt[DD];
    int t = c >> 4;
    if (d < DD) { e[d] = d_embE[c * DD + d]; mt[d] = d_meanT[t * DD + d]; }
    __syncthreads();
    if (d < DD) {
        float acc = ba1[d];
        for (int k = 0; k < DD; k++) acc += e[k] * Wa1[k * DD + d];
        for (int k = 0; k < DD; k++) acc += mt[k] * Wa1[(DD + k) * DD + d];
        d_h2[c * DD + d] = acc;
    }
}

__global__ void k_bnstat2p() {
    int d = blockIdx.x, tid = threadIdx.x;
    __shared__ double rs[128], rs2[128];
    double s = 0.0, s2 = 0.0;
    for (int c = tid; c < NCOMBO; c += 128) {
        double w = (double)d_cntE[c], v = (double)d_h2[c * DD + d];
        s += w * v; s2 += w * v * v;
    }
    rs[tid] = s; rs2[tid] = s2;
    __syncthreads();
    for (int o = 64; o > 0; o >>= 1) {
        if (tid < o) { rs[tid] += rs[tid + o]; rs2[tid] += rs2[tid + o]; }
        __syncthreads();
    }
    if (tid == 0) {
        double m = rs[0] / (double)EE;
        double var = rs2[0] / (double)EE - m * m;
        d_bn2m[d] = (float)m;
        d_bn2r[d] = rsqrtf((float)var + 1e-5f);
    }
}

__global__ void k_Rtab(const float* __restrict__ Wa2, const float* __restrict__ ba2,
                       const float* __restrict__ g, const float* __restrict__ bt) {
    int c = blockIdx.x, d = threadIdx.x;
    __shared__ float a[DD];
    if (d < DD) {
        float v = (d_h2[c * DD + d] - d_bn2m[d]) * d_bn2r[d] * g[d] + bt[d];
        a[d] = fmaxf(v, 0.f);
    }
    __syncthreads();
    if (d < DD) {
        float acc = 0.f;
        for (int k = 0; k < DD; k++) acc += a[k] * Wa2[k * DD + d];
        d_Rtab[c * DD + d] = acc + ba2[d];
    }
}

// ------------------------- fused graph attention -------------------------
__global__ __launch_bounds__(256) void k_attn(const float* __restrict__ sent,
                                              const float* __restrict__ Watt) {
    int b = blockIdx.x, tid = threadIdx.x;
    __shared__ float sv[DD], q[DD];
    __shared__ float Pb[NCOMBO], Wacc[NCOMBO];
    __shared__ float red[256];
    if (tid < DD) sv[tid] = sent[b * DD + tid];
    for (int i = tid; i < NCOMBO; i += 256) Wacc[i] = 0.f;
    __syncthreads();
    if (tid < DD) {
        float a = 0.f;
        for (int k = 0; k < DD; k++) a += sv[k] * Watt[k * DD + tid];
        q[tid] = a * 0.07071067811865475f;   // 1/sqrt(200)
    }
    __syncthreads();
    int lane = tid & 31, w = tid >> 5;
    for (int c = w; c < NCOMBO; c += 8) {
        float p = 0.f;
        for (int k = lane; k < DD; k += 32) p += q[k] * d_Rtab[c * DD + k];
        for (int o = 16; o > 0; o >>= 1) p += __shfl_down_sync(0xffffffffu, p, o);
        if (lane == 0) Pb[c] = p;
    }
    __syncthreads();
    int cid[4]; float sc[4]; float lmax = -1e30f;
#pragma unroll
    for (int j = 0; j < 4; j++) {
        int e = b * LL + tid + j * 256;
        cid[j] = d_combo[e];
        sc[j] = Pb[cid[j]];
        lmax = fmaxf(lmax, sc[j]);
    }
    red[tid] = lmax; __syncthreads();
    for (int s = 128; s > 0; s >>= 1) { if (tid < s) red[tid] = fmaxf(red[tid], red[tid + s]); __syncthreads(); }
    float bmax = red[0]; __syncthreads();
    float lsum = 0.f;
#pragma unroll
    for (int j = 0; j < 4; j++) { sc[j] = expf(sc[j] - bmax); lsum += sc[j]; }
    red[tid] = lsum; __syncthreads();
    for (int s = 128; s > 0; s >>= 1) { if (tid < s) red[tid] += red[tid + s]; __syncthreads(); }
    float inv = 1.f / red[0]; __syncthreads();
#pragma unroll
    for (int j = 0; j < 4; j++) atomicAdd(&Wacc[cid[j]], sc[j] * inv);
    __syncthreads();
    if (tid < DD) {
        float a = 0.f;
        for (int c = 0; c < NCOMBO; c++) a += Wacc[c] * d_Rtab[c * DD + tid];
        d_upd[b * DD + tid] = a;
    }
}

__global__ void k_ukum(const float* __restrict__ Wk, const float* __restrict__ Wm) {
    int id = blockIdx.x, d = threadIdx.x;
    __shared__ float s[DD];
    const float* srow = (id < BB) ? &d_upd[id * DD] : &d_embS[(id - BB) * DD];
    if (d < DD) s[d] = srow[d];
    __syncthreads();
    if (d < DD) {
        float ak = 0.f, am = 0.f;
        for (int k = 0; k < DD; k++) {
            float sv = s[k];
            ak += sv * Wk[(DD + k) * DD + d];
            am += sv * Wm[(DD + k) * DD + d];
        }
        d_UKall[id * DD + d] = ak;
        d_UMall[id * DD + d] = am;
    }
}

// ------------------------- weight packing -------------------------
__global__ void k_pack(const float* __restrict__ Wk, const float* __restrict__ Wm,
                       const float* __restrict__ Wq,
                       const float* __restrict__ bk, const float* __restrict__ bm,
                       const float* __restrict__ bq,
                       const float* __restrict__ Wo1, const float* __restrict__ Wo2) {
    const float invs = 0.1414213562373095f;   // 1/sqrt(50)
    int i = blockIdx.x * blockDim.x + threadIdx.x;
    if (i < DD * 640) {
        int k = i / 640, c = i % 640;
        float v = (c < DD) ? Wk[k * DD + c]
                : (c < 2 * DD) ? Wm[k * DD + (c - DD)]
                : (c < 3 * DD) ? Wq[k * DD + (c - 2 * DD)] * invs : 0.f;
        d_Wcat[i] = v;
        return;
    }
    int j = i - DD * 640;
    if (j < DD * 256) {
        int k = j >> 8, c = j & 255;
        d_Wo1P[j] = (c < DD) ? Wo1[k * DD + c] : 0.f;
        return;
    }
    j -= DD * 256;
    if (j < DD * 256) {
        int k = j >> 8, c = j & 255;
        d_Wo2P[j] = (c < DD) ? Wo2[k * DD + c] : 0.f;
        return;
    }
    j -= DD * 256;
    if (j < 640) {
        float v = (j < DD) ? bk[j]
                : (j < 2 * DD) ? bm[j - DD]
                : (j < 3 * DD) ? bq[j - 2 * DD] * invs : 0.f;
        d_bcat[j] = v;
    }
}

// ------------------------- tf32 GEMM: 128x128 tile, 2-stage smem pipeline -------------------------
template<int DOSTAT>
__global__ __launch_bounds__(256, 2) void k_gemmT(
    int M, int Nreal, int K,
    const float* __restrict__ A, int lda,
    const float* __restrict__ B, int ldb,
    float* __restrict__ C, int ldc,
    const float* __restrict__ bias,
    const float* __restrict__ bnm, const float* __restrict__ bnr,
    const float* __restrict__ bng, const float* __restrict__ bnb) {
    __shared__ uint32_t As[2][8][132];
    __shared__ uint32_t Bs[2][8][132];
    __shared__ float cs[128], cs2[128];
    int tid = threadIdx.x;
    int lane = tid & 31, warp = tid >> 5;
    int wm = warp >> 2, wn = warp & 3;
    int gid = lane >> 2, tg = lane & 3;
    int row0 = blockIdx.y * 128, col0 = blockIdx.x * 128;
    if (DOSTAT && tid < 128) { cs[tid] = 0.f; cs2[tid] = 0.f; }

    float acc[4][4][4];
#pragma unroll
    for (int mt = 0; mt < 4; mt++)
#pragma unroll
        for (int nt = 0; nt < 4; nt++)
#pragma unroll
            for (int r = 0; r < 4; r++) acc[mt][nt][r] = 0.f;

    int rowA = row0 + (tid >> 1);
    int kA = (tid & 1) * 4;
    int rowB = tid >> 5;
    int colB = (tid & 31) * 4;
    int m0 = wm * 64, n0 = wn * 32;
    int mrow = tid >> 1;
    int nk = K / 8;

    float4 av, bv;
    {
        av = *(const float4*)&A[(size_t)rowA * lda + kA];
        if (bnm) {
            int g = kA;
            av.x = fmaxf((av.x - bnm[g])     * bnr[g]     * bng[g]     + bnb[g],     0.f);
            av.y = fmaxf((av.y - bnm[g + 1]) * bnr[g + 1] * bng[g + 1] + bnb[g + 1], 0.f);
            av.z = fmaxf((av.z - bnm[g + 2]) * bnr[g + 2] * bng[g + 2] + bnb[g + 2], 0.f);
            av.w = fmaxf((av.w - bnm[g + 3]) * bnr[g + 3] * bng[g + 3] + bnb[g + 3], 0.f);
        }
        bv = *(const float4*)&B[(size_t)rowB * ldb + col0 + colB];
        uint32_t u0, u1, u2, u3;
        CVT_TF32(u0, av.x); CVT_TF32(u1, av.y); CVT_TF32(u2, av.z); CVT_TF32(u3, av.w);
        As[0][kA + 0][mrow] = u0; As[0][kA + 1][mrow] = u1;
        As[0][kA + 2][mrow] = u2; As[0][kA + 3][mrow] = u3;
        CVT_TF32(u0, bv.x); CVT_TF32(u1, bv.y); CVT_TF32(u2, bv.z); CVT_TF32(u3, bv.w);
        Bs[0][rowB][colB] = u0; Bs[0][rowB][colB + 1] = u1;
        Bs[0][rowB][colB + 2] = u2; Bs[0][rowB][colB + 3] = u3;
    }

    for (int kt = 0; kt < nk; kt++) {
        int cur = kt & 1;
        int nxt = cur ^ 1;
        bool has = (kt + 1 < nk);
        if (has) {
            int k0 = (kt + 1) * 8;
            av = *(const float4*)&A[(size_t)rowA * lda + k0 + kA];
            if (bnm) {
                int g = k0 + kA;
                av.x = fmaxf((av.x - bnm[g])     * bnr[g]     * bng[g]     + bnb[g],     0.f);
                av.y = fmaxf((av.y - bnm[g + 1]) * bnr[g + 1] * bng[g + 1] + bnb[g + 1], 0.f);
                av.z = fmaxf((av.z - bnm[g + 2]) * bnr[g + 2] * bng[g + 2] + bnb[g + 2], 0.f);
                av.w = fmaxf((av.w - bnm[g + 3]) * bnr[g + 3] * bng[g + 3] + bnb[g + 3], 0.f);
            }
            bv = *(const float4*)&B[(size_t)(k0 + rowB) * ldb + col0 + colB];
        }
        __syncthreads();
        if (has) {
            uint32_t u0, u1, u2, u3;
            CVT_TF32(u0, av.x); CVT_TF32(u1, av.y); CVT_TF32(u2, av.z); CVT_TF32(u3, av.w);
            As[nxt][kA + 0][mrow] = u0; As[nxt][kA + 1][mrow] = u1;
            As[nxt][kA + 2][mrow] = u2; As[nxt][kA + 3][mrow] = u3;
            CVT_TF32(u0, bv.x); CVT_TF32(u1, bv.y); CVT_TF32(u2, bv.z); CVT_TF32(u3, bv.w);
            Bs[nxt][rowB][colB] = u0; Bs[nxt][rowB][colB + 1] = u1;
            Bs[nxt][rowB][colB + 2] = u2; Bs[nxt][rowB][colB + 3] = u3;
        }
        uint32_t af[4][4], bf[4][2];
#pragma unroll
        for (int mt = 0; mt < 4; mt++) {
            int mb = m0 + mt * 16 + gid;
            af[mt][0] = As[cur][tg][mb];
            af[mt][1] = As[cur][tg][mb + 8];
            af[mt][2] = As[cur][tg + 4][mb];
            af[mt][3] = As[cur][tg + 4][mb + 8];
        }
#pragma unroll
        for (int nt = 0; nt < 4; nt++) {
            int nb = n0 + nt * 8 + gid;
            bf[nt][0] = Bs[cur][tg][nb];
            bf[nt][1] = Bs[cur][tg + 4][nb];
        }
#pragma unroll
        for (int mt = 0; mt < 4; mt++)
#pragma unroll
            for (int nt = 0; nt < 4; nt++)
                MMA_TF32(acc[mt][nt][0], acc[mt][nt][1], acc[mt][nt][2], acc[mt][nt][3],
                         af[mt][0], af[mt][1], af[mt][2], af[mt][3],
                         bf[nt][0], bf[nt][1]);
    }

    float colS[4][2], colS2[4][2];
#pragma unroll
    for (int nt = 0; nt < 4; nt++) { colS[nt][0] = colS[nt][1] = 0.f; colS2[nt][0] = colS2[nt][1] = 0.f; }
#pragma unroll
    for (int mt = 0; mt < 4; mt++) {
        int r = row0 + m0 + mt * 16 + gid;
#pragma unroll
        for (int nt = 0; nt < 4; nt++) {
            int c = col0 + n0 + nt * 8 + tg * 2;
            float b0 = (bias && c < Nreal)     ? bias[c]     : 0.f;
            float b1 = (bias && c + 1 < Nreal) ? bias[c + 1] : 0.f;
            float v0 = acc[mt][nt][0] + b0;
            float v1 = acc[mt][nt][1] + b1;
            float v2 = acc[mt][nt][2] + b0;
            float v3 = acc[mt][nt][3] + b1;
            float* cr0 = &C[(size_t)r * ldc];
            float* cr1 = &C[(size_t)(r + 8) * ldc];
            if (c < Nreal)     { cr0[c] = v0; cr1[c] = v2; }
            if (c + 1 < Nreal) { cr0[c + 1] = v1; cr1[c + 1] = v3; }
            if (DOSTAT) {
                colS[nt][0]  += v0 + v2;
                colS2[nt][0] += v0 * v0 + v2 * v2;
                colS[nt][1]  += v1 + v3;
                colS2[nt][1] += v1 * v1 + v3 * v3;
            }
        }
    }
    if (DOSTAT) {
#pragma unroll
        for (int nt = 0; nt < 4; nt++) {
#pragma unroll
            for (int p = 0; p < 2; p++) {
                float a = colS[nt][p], b = colS2[nt][p];
                for (int o = 16; o >= 4; o >>= 1) {
                    a += __shfl_down_sync(0xffffffffu, a, o);
                    b += __shfl_down_sync(0xffffffffu, b, o);
                }
                colS[nt][p] = a; colS2[nt][p] = b;
            }
        }
        __syncthreads();
        if (gid == 0) {
#pragma unroll
            for (int nt = 0; nt < 4; nt++) {
                int lc = n0 + nt * 8 + tg * 2;
                atomicAdd(&cs[lc],      colS[nt][0]);
                atomicAdd(&cs2[lc],     colS2[nt][0]);
                atomicAdd(&cs[lc + 1],  colS[nt][1]);
                atomicAdd(&cs2[lc + 1], colS2[nt][1]);
            }
        }
        __syncthreads();
        if (tid < 128) {
            int gc = col0 + tid;
            if (gc < Nreal) {
                atomicAdd(&d_colsum[gc],  cs[tid]);
                atomicAdd(&d_colsum2[gc], cs2[tid]);
            }
        }
    }
}

// ------------------------- edge attention: warp-per-src via src-CSR -------------------------
__global__ __launch_bounds__(256) void k_D1s(const int* __restrict__ ei,
                                             const int* __restrict__ ntp) {
    int gw = (blockIdx.x * blockDim.x + threadIdx.x) >> 5;
    int lane = threadIdx.x & 31;
    int w = threadIdx.x >> 5;
    __shared__ float sq[8][DD];
    if (gw >= NN) return;
    int n = gw;
    const float* qrow = &d_XKMQ[(size_t)n * 600 + 400];
    for (int c = lane; c < DD; c += 32) sq[w][c] = qrow[c];
    __syncwarp();
    int h = lane >> 3, r = lane & 7;
    float denacc = 0.f;
    int beg = d_srcOff[n], end = d_srcOff[n + 1];
    for (int e = beg; e < end; e++) {
        int i = d_csrS[e];
        int dd, kidx;
        if (i < EE) { dd = ei[EE + i]; kidx = i >> 10; }
        else { dd = n; kidx = BB + ntp[n]; }
        const float* krow = &d_XKMQ[(size_t)dd * 600];
        const float* kadd = &d_UKall[kidx * DD];
        float p = 0.f;
#pragma unroll
        for (int j = 0; j < 4; j++) {
            int idx = r + 8 * j;
            if (idx < 25) {
                int d0 = h * 50 + idx * 2;
                float2 k2 = *(const float2*)(krow + d0);
                float2 a2 = *(const float2*)(kadd + d0);
                p += sq[w][d0] * (k2.x + a2.x) + sq[w][d0 + 1] * (k2.y + a2.y);
            }
        }
        p += __shfl_down_sync(0xffffffffu, p, 4);
        p += __shfl_down_sync(0xffffffffu, p, 2);
        p += __shfl_down_sync(0xffffffffu, p, 1);
        if (r == 0) {
            float exv = __expf(p);
            d_ex[(size_t)i * 4 + h] = exv;
            denacc += exv;
        }
    }
    if (r == 0) d_den[n * 4 + h] = denacc;
}

// ------------------------- aggregation: one warp per dst node -------------------------
__global__ __launch_bounds__(256) void k_D2w(const int* __restrict__ ei,
                                             const int* __restrict__ ntp) {
    int gw = (blockIdx.x * blockDim.x + threadIdx.x) >> 5;
    int lane = threadIdx.x & 31;
    int w = threadIdx.x >> 5;
    if (gw >= NN) return;
    int n = gw;
    int beg = d_dstOff[n], end = d_dstOff[n + 1];
    __shared__ float s_al[8][16][4];
    __shared__ int s_j[8][16], s_u[8][16];
    float acc[7];
#pragma unroll
    for (int k = 0; k < 7; k++) acc[k] = 0.f;
    for (int base = beg; base < end; base += 16) {
        int cnt = min(16, end - base);
        if (lane < cnt) {
            int i = d_csr[base + lane];
            int s, j, u;
            if (i < EE) { s = ei[i]; j = s; u = i >> 10; }
            else { int nn2 = i - EE; s = nn2; j = nn2; u = BB + ntp[nn2]; }
            s_j[w][lane] = j;
            s_u[w][lane] = u;
            float csf = (float)d_cntSrc[s];
#pragma unroll
            for (int hh = 0; hh < 4; hh++)
                s_al[w][lane][hh] = __fdividef(d_ex[(size_t)i * 4 + hh], d_den[s * 4 + hh]) * csf;
        }
        __syncwarp();
        for (int r = 0; r < cnt; r++) {
            const float* mrow = &d_XKMQ[(size_t)s_j[w][r] * 600 + 200];
            const float* urow = &d_UMall[s_u[w][r] * DD];
            float a0 = s_al[w][r][0], a1 = s_al[w][r][1];
            float a2 = s_al[w][r][2], a3 = s_al[w][r][3];
#pragma unroll
            for (int k = 0; k < 7; k++) {
                int c = lane + 32 * k;
                if (c < DD) {
                    float al = c < 50 ? a0 : c < 100 ? a1 : c < 150 ? a2 : a3;
                    acc[k] += al * (mrow[c] + urow[c]);
                }
            }
        }
        __syncwarp();
    }
#pragma unroll
    for (int k = 0; k < 7; k++) {
        int c = lane + 32 * k;
        if (c < DD) d_aggr[(size_t)n * DD + c] = acc[k];
    }
}

__global__ void k_stat3() {
    int d = threadIdx.x;
    if (d >= DD) return;
    float m = d_colsum[d] / (float)NN;
    float var = d_colsum2[d] / (float)NN - m * m;
    d_bn3m[d] = m;
    d_bn3r[d] = rsqrtf(var + 1e-5f);
}

// ------------------------- launch (forked graph: 4-way overlap) -------------------------
extern "C" void kernel_launch(void* const* d_in, const int* in_sizes, int n_in,
                              void* d_out, int out_size) {
    const float* x    = (const float*)d_in[0];
    const float* sent = (const float*)d_in[2];
    const float* We1  = (const float*)d_in[3];
    const float* be1  = (const float*)d_in[4];
    const float* ge1  = (const float*)d_in[5];
    const float* bte1 = (const float*)d_in[6];
    const float* We2  = (const float*)d_in[7];
    const float* be2  = (const float*)d_in[8];
    const float* Wa1  = (const float*)d_in[9];
    const float* ba1  = (const float*)d_in[10];
    const float* ga1  = (const float*)d_in[11];
    const float* bta1 = (const float*)d_in[12];
    const float* Wa2  = (const float*)d_in[13];
    const float* ba2  = (const float*)d_in[14];
    const float* Watt = (const float*)d_in[15];
    const float* Wk   = (const float*)d_in[16];
    const float* bk   = (const float*)d_in[17];
    const float* Wm   = (const float*)d_in[18];
    const float* bm   = (const float*)d_in[19];
    const float* Wq   = (const float*)d_in[20];
    const float* bq   = (const float*)d_in[21];
    const float* Wo1  = (const float*)d_in[22];
    const float* bo1  = (const float*)d_in[23];
    const float* go1  = (const float*)d_in[24];
    const float* bto1 = (const float*)d_in[25];
    const float* Wo2  = (const float*)d_in[26];
    const float* bo2  = (const float*)d_in[27];
    const int* ei     = (const int*)d_in[28];
    const int* et     = (const int*)d_in[29];
    const int* ntp    = (const int*)d_in[30];
    float* out = (float*)d_out;

    void* tmp;
    cudaGetSymbolAddress(&tmp, d_Wcat);  float* pWcat = (float*)tmp;
    cudaGetSymbolAddress(&tmp, d_bcat);  float* pbcat = (float*)tmp;
    cudaGetSymbolAddress(&tmp, d_Wo1P);  float* pWo1P = (float*)tmp;
    cudaGetSymbolAddress(&tmp, d_Wo2P);  float* pWo2P = (float*)tmp;
    cudaGetSymbolAddress(&tmp, d_XKMQ);  float* pXKMQ = (float*)tmp;
    cudaGetSymbolAddress(&tmp, d_aggr);  float* pAggr = (float*)tmp;
    cudaGetSymbolAddress(&tmp, d_Y1);    float* pY1   = (float*)tmp;
    cudaGetSymbolAddress(&tmp, d_bn3m);  float* pb3m  = (float*)tmp;
    cudaGetSymbolAddress(&tmp, d_bn3r);  float* pb3r  = (float*)tmp;

    static cudaStream_t sA = nullptr, sB = nullptr, sC = nullptr;
    static cudaEvent_t evStart = nullptr, evH = nullptr, evA = nullptr, evB = nullptr, evC = nullptr;
    if (!sA) {
        cudaStreamCreateWithFlags(&sA, cudaStreamNonBlocking);
        cudaStreamCreateWithFlags(&sB, cudaStreamNonBlocking);
        cudaStreamCreateWithFlags(&sC, cudaStreamNonBlocking);
        cudaEventCreateWithFlags(&evStart, cudaEventDisableTiming);
        cudaEventCreateWithFlags(&evH, cudaEventDisableTiming);
        cudaEventCreateWithFlags(&evA, cudaEventDisableTiming);
        cudaEventCreateWithFlags(&evB, cudaEventDisableTiming);
        cudaEventCreateWithFlags(&evC, cudaEventDisableTiming);
    }

    // Fork branch A at graph root: pack weights + big XKMQ GEMM (independent of everything else).
    cudaEventRecord(evStart, 0);
    cudaStreamWaitEvent(sA, evStart, 0);
    k_pack<<<(DD * 640 + 2 * DD * 256 + 640 + 255) / 256, 256, 0, sA>>>(Wk, Wm, Wq, bk, bm, bq, Wo1, Wo2);
    {   // XKMQ = x @ [Wk1|Wm1|Wq*invs] + [bk|bm|bq*invs]
        dim3 g(5, NN / 128);
        k_gemmT<0><<<g, 256, 0, sA>>>(NN, 600, DD, x, DD, pWcat, 640, pXKMQ, 600,
                                      pbcat, nullptr, nullptr, nullptr, nullptr);
    }
    cudaEventRecord(evA, sA);

    // Main stream: zero + edge histogram.
    k_zero<<<1024, 256>>>(ntp);
    k_edgehist<<<EE / 1024, 256>>>(ei, et, ntp);
    cudaEventRecord(evH, 0);

    // Fork branch B after edgehist: dual CSR build (dst + src).
    cudaStreamWaitEvent(sB, evH, 0);
    k_scanA2<<<dim3(50, 2), 1024, 0, sB>>>();
    k_scanB2<<<2, 64, 0, sB>>>();
    k_scanC2<<<dim3(50, 2), 1024, 0, sB>>>();
    k_csrfill<<<(TOTROWS + 255) / 256, 256, 0, sB>>>(ei);
    cudaEventRecord(evB, sB);

    // Fork branch C after edgehist: combo tables + BN1 + emb (independent of segsum).
    cudaStreamWaitEvent(sC, evH, 0);
    k_tables<<<NCOMBO + NTY, 256, 0, sC>>>(We1, be1);
    k_bnstat1p<<<DD, 128, 0, sC>>>();
    k_emb<<<NCOMBO + NTY, 256, 0, sC>>>(We2, be2, ge1, bte1);
    cudaEventRecord(evC, sC);

    // Main stream: segment sums (overlaps with A, B, C).
    k_segsum3<<<400, 128>>>(x);
    k_meanT<<<(NT1 * DD + 255) / 256, 256>>>();

    // Join C (embE/embS ready), then rest of the table chain.
    cudaStreamWaitEvent(0, evC, 0);
    k_h2pre<<<NCOMBO, 256>>>(Wa1, ba1);
    k_bnstat2p<<<DD, 128>>>();
    k_Rtab<<<NCOMBO, 256>>>(Wa2, ba2, ga1, bta1);
    k_attn<<<BB, 256>>>(sent, Watt);
    k_ukum<<<BB + NTY, 256>>>(Wk, Wm);

    // Join A (XKMQ) and B (CSRs) before the edge passes.
    cudaStreamWaitEvent(0, evA, 0);
    cudaStreamWaitEvent(0, evB, 0);
    k_D1s<<<NN / 8, 256>>>(ei, ntp);
    k_D2w<<<NN / 8, 256>>>(ei, ntp);
    {   // Y1 = aggr @ Wo1 + bo1  (+ fused column stats)
        dim3 g(2, NN / 128);
        k_gemmT<1><<<g, 256>>>(NN, DD, DD, pAggr, DD, pWo1P, 256, pY1, DD,
                               bo1, nullptr, nullptr, nullptr, nullptr);
    }
    k_stat3<<<1, 256>>>();
    {   // out = relu(bn(Y1)) @ Wo2 + bo2
        dim3 g(2, NN / 128);
        k_gemmT<0><<<g, 256>>>(NN, DD, DD, pY1, DD, pWo2P, 256, out, DD,
                               bo2, pb3m, pb3r, go1, bto1);
    }
}

// round 14
// speedup vs baseline: 1.0111x; 1.0111x over previous
#include <cuda_runtime.h>
#include <math.h>
#include <stdint.h>

#define DD 200
#define NTY 4
#define NET 38
#define NT1 39
#define BB 256
#define LL 1024
#define EE 262144
#define NN 51200
#define NCOMBO 608
#define TOTROWS (EE + NN)

// f32x2 packed-math helpers
#define FMA2(d,a,b)  asm("fma.rn.f32x2 %0, %1, %2, %3;" : "=l"(d) : "l"(a), "l"(b), "l"(d))
#define PACK2(d,x,y) asm("mov.b64 %0, {%1, %2};" : "=l"(d) : "f"(x), "f"(y))
#define UNPACK2(x,y,d) asm("mov.b64 {%0, %1}, %2;" : "=f"(x), "=f"(y) : "l"(d))

#define CVT_TF32(u,f) asm("cvt.rna.tf32.f32 %0, %1;" : "=r"(u) : "f"(f))
#define MMA_TF32(c0,c1,c2,c3,a0,a1,a2,a3,b0,b1) \
  asm("mma.sync.aligned.m16n8k8.row.col.f32.tf32.tf32.f32 " \
      "{%0,%1,%2,%3},{%4,%5,%6,%7},{%8,%9},{%0,%1,%2,%3};" \
      : "+f"(c0),"+f"(c1),"+f"(c2),"+f"(c3) \
      : "r"(a0),"r"(a1),"r"(a2),"r"(a3),"r"(b0),"r"(b1))

// ------------------------- scratch -------------------------
__device__ float d_coeff[(size_t)NN * NT1];
__device__ float d_sums[NT1 * DD];
__device__ int   d_cntT[NT1];
__device__ int   d_cntE[NCOMBO];
__device__ int   d_cntN[NTY];
__device__ int   d_combo[EE];
__device__ int   d_cntSrc[NN];
__device__ int   d_dstCnt[NN];
__device__ int   d_dstOff[NN + 1];
__device__ int   d_cursor[NN];
__device__ int   d_csr[TOTROWS];
__device__ int   d_blkSum[50];
__device__ float d_meanT[NT1 * DD];
__device__ float d_preE[NCOMBO * DD];
__device__ float d_preS[NTY * DD];
__device__ float d_embE[NCOMBO * DD];
__device__ float d_embS[NTY * DD];
__device__ float d_h2[NCOMBO * DD];
__device__ float d_Rtab[NCOMBO * DD];
__device__ float d_bn1m[DD], d_bn1r[DD], d_bn2m[DD], d_bn2r[DD], d_bn3m[DD], d_bn3r[DD];
__device__ float d_upd[BB * DD];
__device__ float d_UKall[(BB + NTY) * DD];
__device__ float d_UMall[(BB + NTY) * DD];
__device__ float d_Wcat[DD * 640];
__device__ float d_bcat[640];
__device__ float d_Wo1P[DD * 256];
__device__ float d_Wo2P[DD * 256];
__device__ float d_XKMQ[(size_t)NN * 600];    // per-node [XK+bk | XM+bm | (XQ+bq)*invs]
__device__ float d_ex[(size_t)TOTROWS * 4];
__device__ float d_den[NN * 4];
__device__ float d_aggr[(size_t)NN * DD];
__device__ float d_Y1[(size_t)NN * DD];
__device__ double d_colsum[DD], d_colsum2[DD];   // fp64: kills ordering noise in BN3 var

// ------------------------- zero init + node hist (fused) -------------------------
__global__ void k_zero(const int* __restrict__ ntp) {
    long long i0 = (long long)blockIdx.x * blockDim.x + threadIdx.x;
    long long st = (long long)gridDim.x * blockDim.x;
    for (long long i = i0; i < (long long)NT1 * NN; i += st) d_coeff[i] = 0.f;
    for (long long i = i0; i < (long long)NN * 4; i += st) d_den[i] = 0.f;
    for (long long i = i0; i < NT1 * DD; i += st) d_sums[i] = 0.f;
    for (long long i = i0; i < NCOMBO; i += st) d_cntE[i] = 0;
    for (long long i = i0; i < NT1; i += st) d_cntT[i] = 0;
    for (long long i = i0; i < NTY; i += st) d_cntN[i] = 0;
    for (long long i = i0; i < DD; i += st) { d_colsum[i] = 0.0; d_colsum2[i] = 0.0; }
    for (long long i = i0; i < NN; i += st) {
        d_cntSrc[i] = 1;
        d_dstCnt[i] = 1;
        atomicAdd(&d_cntN[ntp[i]], 1);
    }
}

// smem histograms + 4 edges/thread for atomic-chain ILP
__global__ void k_edgehist(const int* __restrict__ ei, const int* __restrict__ et,
                           const int* __restrict__ ntp) {
    __shared__ int sT[NT1];
    __shared__ int sE[NCOMBO];
    int tid = threadIdx.x;
    for (int i = tid; i < NT1; i += 256) sT[i] = 0;
    for (int i = tid; i < NCOMBO; i += 256) sE[i] = 0;
    __syncthreads();
    int e0 = blockIdx.x * 1024 + tid;
    int s[4], dd[4], t[4];
#pragma unroll
    for (int j = 0; j < 4; j++) {
        int e = e0 + j * 256;
        s[j]  = ei[e];
        dd[j] = ei[EE + e];
        t[j]  = et[e];
    }
#pragma unroll
    for (int j = 0; j < 4; j++)
        atomicAdd(&d_coeff[(size_t)dd[j] * NT1 + t[j]], 1.f);
#pragma unroll
    for (int j = 0; j < 4; j++)
        atomicAdd(&d_coeff[(size_t)s[j] * NT1 + t[j]], -1.f);
#pragma unroll
    for (int j = 0; j < 4; j++) {
        int e = e0 + j * 256;
        atomicAdd(&sT[t[j]], 1);
        int c = (t[j] << 4) | (ntp[s[j]] << 2) | ntp[dd[j]];
        d_combo[e] = c;
        atomicAdd(&sE[c], 1);
    }
#pragma unroll
    for (int j = 0; j < 4; j++) atomicAdd(&d_cntSrc[s[j]], 1);
#pragma unroll
    for (int j = 0; j < 4; j++) atomicAdd(&d_dstCnt[dd[j]], 1);
    __syncthreads();
    for (int i = tid; i < NT1; i += 256) if (sT[i]) atomicAdd(&d_cntT[i], sT[i]);
    for (int i = tid; i < NCOMBO; i += 256) if (sE[i]) atomicAdd(&d_cntE[i], sE[i]);
}

// ------------------------- dst-CSR build (3-phase parallel scan) -------------------------
__global__ void k_scanA() {
    __shared__ int sm[1024];
    int tid = threadIdx.x;
    sm[tid] = d_dstCnt[blockIdx.x * 1024 + tid];
    __syncthreads();
    for (int o = 512; o > 0; o >>= 1) {
        if (tid < o) sm[tid] += sm[tid + o];
        __syncthreads();
    }
    if (tid == 0) d_blkSum[blockIdx.x] = sm[0];
}

__global__ void k_scanB() {
    __shared__ int sm[64];
    int tid = threadIdx.x;
    int v = (tid < 50) ? d_blkSum[tid] : 0;
    sm[tid] = v;
    __syncthreads();
    for (int o = 1; o < 64; o <<= 1) {
        int t = (tid >= o) ? sm[tid - o] : 0;
        __syncthreads();
        sm[tid] += t;
        __syncthreads();
    }
    if (tid < 50) d_blkSum[tid] = sm[tid] - v;
    if (tid == 49) d_dstOff[NN] = sm[49];
}

__global__ void k_scanC() {
    __shared__ int sm[1024];
    int tid = threadIdx.x;
    int g = blockIdx.x * 1024 + tid;
    int v = d_dstCnt[g];
    sm[tid] = v;
    __syncthreads();
    for (int o = 1; o < 1024; o <<= 1) {
        int t = (tid >= o) ? sm[tid - o] : 0;
        __syncthreads();
        sm[tid] += t;
        __syncthreads();
    }
    int excl = sm[tid] - v + d_blkSum[blockIdx.x];
    d_dstOff[g] = excl;
    d_cursor[g] = excl;
}

__global__ void k_csrfill(const int* __restrict__ ei) {
    int i = blockIdx.x * blockDim.x + threadIdx.x;
    if (i >= TOTROWS) return;
    int dst = (i < EE) ? ei[EE + i] : (i - EE);
    int pos = atomicAdd(&d_cursor[dst], 1);
    d_csr[pos] = i;
}

// ------------------------- segment sums -------------------------
__global__ __launch_bounds__(128) void k_segsum3(const float* __restrict__ x) {
    __shared__ unsigned long long cf2[128][NT1];
    int tid = threadIdx.x;
    int n0 = blockIdx.x * 128;
    for (int i = tid; i < 128 * NT1; i += 128) {
        float c = d_coeff[(size_t)(n0 + i / NT1) * NT1 + (i % NT1)];
        unsigned long long c2; PACK2(c2, c, c);
        cf2[i / NT1][i % NT1] = c2;
    }
    __syncthreads();
    if (tid < 100) {
        unsigned long long acc[NT1];
#pragma unroll
        for (int t = 0; t < NT1; t++) acc[t] = 0ULL;
        for (int nn = 0; nn < 128; nn++) {
            float2 xv = *(const float2*)&x[(size_t)(n0 + nn) * DD + tid * 2];
            unsigned long long xv2; PACK2(xv2, xv.x, xv.y);
#pragma unroll
            for (int t = 0; t < NT1; t++)
                FMA2(acc[t], cf2[nn][t], xv2);
        }
#pragma unroll
        for (int t = 0; t < NT1; t++) {
            float lo, hi; UNPACK2(lo, hi, acc[t]);
            if (lo != 0.f) atomicAdd(&d_sums[t * DD + tid * 2], lo);
            if (hi != 0.f) atomicAdd(&d_sums[t * DD + tid * 2 + 1], hi);
        }
    }
}

__global__ void k_meanT() {
    int i = blockIdx.x * blockDim.x + threadIdx.x;
    if (i >= NT1 * DD) return;
    int t = i / DD;
    float c = (float)d_cntT[t];
    if (c < 1.f) c = 1.f;
    d_meanT[i] = d_sums[i] / c;
}

// ------------------------- combo tables -------------------------
__global__ void k_tables(const float* __restrict__ We1, const float* __restrict__ be1) {
    int c = blockIdx.x, d = threadIdx.x;
    if (d >= DD) return;
    if (c < NCOMBO) {
        int t = c >> 4, a = (c >> 2) & 3, b = c & 3;
        d_preE[c * DD + d] = We1[t * DD + d] + We1[(NT1 + a) * DD + d]
                           + We1[(NT1 + NTY + b) * DD + d] + be1[d];
    } else {
        int t = c - NCOMBO;
        d_preS[t * DD + d] = We1[NET * DD + d] + We1[(NT1 + t) * DD + d]
                           + We1[(NT1 + NTY + t) * DD + d] + be1[d];
    }
}

__global__ void k_bnstat1p() {
    int d = blockIdx.x, tid = threadIdx.x;
    __shared__ double rs[128], rs2[128];
    double s = 0.0, s2 = 0.0;
    for (int c = tid; c < NCOMBO; c += 128) {
        double w = (double)d_cntE[c], v = (double)d_preE[c * DD + d];
        s += w * v; s2 += w * v * v;
    }
    if (tid < NTY) {
        double w = (double)d_cntN[tid], v = (double)d_preS[tid * DD + d];
        s += w * v; s2 += w * v * v;
    }
    rs[tid] = s; rs2[tid] = s2;
    __syncthreads();
    for (int o = 64; o > 0; o >>= 1) {
        if (tid < o) { rs[tid] += rs[tid + o]; rs2[tid] += rs2[tid + o]; }
        __syncthreads();
    }
    if (tid == 0) {
        double m = rs[0] / (double)TOTROWS;
        double var = rs2[0] / (double)TOTROWS - m * m;
        d_bn1m[d] = (float)m;
        d_bn1r[d] = rsqrtf((float)var + 1e-5f);
    }
}

__global__ void k_emb(const float* __restrict__ We2, const float* __restrict__ be2,
                      const float* __restrict__ g, const float* __restrict__ bt) {
    int c = blockIdx.x, d = threadIdx.x;
    __shared__ float a[DD];
    const float* srow = (c < NCOMBO) ? &d_preE[c * DD] : &d_preS[(c - NCOMBO) * DD];
    if (d < DD) {
        float v = (srow[d] - d_bn1m[d]) * d_bn1r[d] * g[d] + bt[d];
        a[d] = fmaxf(v, 0.f);
    }
    __syncthreads();
    if (d < DD) {
        float acc = 0.f;
        for (int k = 0; k < DD; k++) acc += a[k] * We2[k * DD + d];
        float* dst = (c < NCOMBO) ? &d_embE[c * DD] : &d_embS[(c - NCOMBO) * DD];
        dst[d] = acc + be2[d];
    }
}

__global__ void k_h2pre(const float* __restrict__ Wa1, const float* __restrict__ ba1) {
    int c = blockIdx.x, d = threadIdx.x;
    __shared__ float e[DD], mt[DD];
    int t = c >> 4;
    if (d < DD) { e[d] = d_embE[c * DD + d]; mt[d] = d_meanT[t * DD + d]; }
    __syncthreads();
    if (d < DD) {
        float acc = ba1[d];
        for (int k = 0; k < DD; k++) acc += e[k] * Wa1[k * DD + d];
        for (int k = 0; k < DD; k++) acc += mt[k] * Wa1[(DD + k) * DD + d];
        d_h2[c * DD + d] = acc;
    }
}

__global__ void k_bnstat2p() {
    int d = blockIdx.x, tid = threadIdx.x;
    __shared__ double rs[128], rs2[128];
    double s = 0.0, s2 = 0.0;
    for (int c = tid; c < NCOMBO; c += 128) {
        double w = (double)d_cntE[c], v = (double)d_h2[c * DD + d];
        s += w * v; s2 += w * v * v;
    }
    rs[tid] = s; rs2[tid] = s2;
    __syncthreads();
    for (int o = 64; o > 0; o >>= 1) {
        if (tid < o) { rs[tid] += rs[tid + o]; rs2[tid] += rs2[tid + o]; }
        __syncthreads();
    }
    if (tid == 0) {
        double m = rs[0] / (double)EE;
        double var = rs2[0] / (double)EE - m * m;
        d_bn2m[d] = (float)m;
        d_bn2r[d] = rsqrtf((float)var + 1e-5f);
    }
}

__global__ void k_Rtab(const float* __restrict__ Wa2, const float* __restrict__ ba2,
                       const float* __restrict__ g, const float* __restrict__ bt) {
    int c = blockIdx.x, d = threadIdx.x;
    __shared__ float a[DD];
    if (d < DD) {
        float v = (d_h2[c * DD + d] - d_bn2m[d]) * d_bn2r[d] * g[d] + bt[d];
        a[d] = fmaxf(v, 0.f);
    }
    __syncthreads();
    if (d < DD) {
        float acc = 0.f;
        for (int k = 0; k < DD; k++) acc += a[k] * Wa2[k * DD + d];
        d_Rtab[c * DD + d] = acc + ba2[d];
    }
}

// ------------------------- fused graph attention -------------------------
__global__ __launch_bounds__(256) void k_attn(const float* __restrict__ sent,
                                              const float* __restrict__ Watt) {
    int b = blockIdx.x, tid = threadIdx.x;
    __shared__ float sv[DD], q[DD];
    __shared__ float Pb[NCOMBO], Wacc[NCOMBO];
    __shared__ float red[256];
    if (tid < DD) sv[tid] = sent[b * DD + tid];
    for (int i = tid; i < NCOMBO; i += 256) Wacc[i] = 0.f;
    __syncthreads();
    if (tid < DD) {
        float a = 0.f;
        for (int k = 0; k < DD; k++) a += sv[k] * Watt[k * DD + tid];
        q[tid] = a * 0.07071067811865475f;   // 1/sqrt(200)
    }
    __syncthreads();
    int lane = tid & 31, w = tid >> 5;
    for (int c = w; c < NCOMBO; c += 8) {
        float p = 0.f;
        for (int k = lane; k < DD; k += 32) p += q[k] * d_Rtab[c * DD + k];
        for (int o = 16; o > 0; o >>= 1) p += __shfl_down_sync(0xffffffffu, p, o);
        if (lane == 0) Pb[c] = p;
    }
    __syncthreads();
    int cid[4]; float sc[4]; float lmax = -1e30f;
#pragma unroll
    for (int j = 0; j < 4; j++) {
        int e = b * LL + tid + j * 256;
        cid[j] = d_combo[e];
        sc[j] = Pb[cid[j]];
        lmax = fmaxf(lmax, sc[j]);
    }
    red[tid] = lmax; __syncthreads();
    for (int s = 128; s > 0; s >>= 1) { if (tid < s) red[tid] = fmaxf(red[tid], red[tid + s]); __syncthreads(); }
    float bmax = red[0]; __syncthreads();
    float lsum = 0.f;
#pragma unroll
    for (int j = 0; j < 4; j++) { sc[j] = expf(sc[j] - bmax); lsum += sc[j]; }
    red[tid] = lsum; __syncthreads();
    for (int s = 128; s > 0; s >>= 1) { if (tid < s) red[tid] += red[tid + s]; __syncthreads(); }
    float inv = 1.f / red[0]; __syncthreads();
#pragma unroll
    for (int j = 0; j < 4; j++) atomicAdd(&Wacc[cid[j]], sc[j] * inv);
    __syncthreads();
    if (tid < DD) {
        float a = 0.f;
        for (int c = 0; c < NCOMBO; c++) a += Wacc[c] * d_Rtab[c * DD + tid];
        d_upd[b * DD + tid] = a;
    }
}

__global__ void k_ukum(const float* __restrict__ Wk, const float* __restrict__ Wm) {
    int id = blockIdx.x, d = threadIdx.x;
    __shared__ float s[DD];
    const float* srow = (id < BB) ? &d_upd[id * DD] : &d_embS[(id - BB) * DD];
    if (d < DD) s[d] = srow[d];
    __syncthreads();
    if (d < DD) {
        float ak = 0.f, am = 0.f;
        for (int k = 0; k < DD; k++) {
            float sv = s[k];
            ak += sv * Wk[(DD + k) * DD + d];
            am += sv * Wm[(DD + k) * DD + d];
        }
        d_UKall[id * DD + d] = ak;
        d_UMall[id * DD + d] = am;
    }
}

// ------------------------- weight packing -------------------------
__global__ void k_pack(const float* __restrict__ Wk, const float* __restrict__ Wm,
                       const float* __restrict__ Wq,
                       const float* __restrict__ bk, const float* __restrict__ bm,
                       const float* __restrict__ bq,
                       const float* __restrict__ Wo1, const float* __restrict__ Wo2) {
    const float invs = 0.1414213562373095f;   // 1/sqrt(50)
    int i = blockIdx.x * blockDim.x + threadIdx.x;
    if (i < DD * 640) {
        int k = i / 640, c = i % 640;
        float v = (c < DD) ? Wk[k * DD + c]
                : (c < 2 * DD) ? Wm[k * DD + (c - DD)]
                : (c < 3 * DD) ? Wq[k * DD + (c - 2 * DD)] * invs : 0.f;
        d_Wcat[i] = v;
        return;
    }
    int j = i - DD * 640;
    if (j < DD * 256) {
        int k = j >> 8, c = j & 255;
        d_Wo1P[j] = (c < DD) ? Wo1[k * DD + c] : 0.f;
        return;
    }
    j -= DD * 256;
    if (j < DD * 256) {
        int k = j >> 8, c = j & 255;
        d_Wo2P[j] = (c < DD) ? Wo2[k * DD + c] : 0.f;
        return;
    }
    j -= DD * 256;
    if (j < 640) {
        float v = (j < DD) ? bk[j]
                : (j < 2 * DD) ? bm[j - DD]
                : (j < 3 * DD) ? bq[j - 2 * DD] * invs : 0.f;
        d_bcat[j] = v;
    }
}

// ------------------------- tf32 GEMM: 128x128 tile, 2-stage smem pipeline -------------------------
template<int DOSTAT>
__global__ __launch_bounds__(256, 2) void k_gemmT(
    int M, int Nreal, int K,
    const float* __restrict__ A, int lda,
    const float* __restrict__ B, int ldb,
    float* __restrict__ C, int ldc,
    const float* __restrict__ bias,
    const float* __restrict__ bnm, const float* __restrict__ bnr,
    const float* __restrict__ bng, const float* __restrict__ bnb) {
    __shared__ uint32_t As[2][8][132];
    __shared__ uint32_t Bs[2][8][132];
    __shared__ double cs[128], cs2[128];
    int tid = threadIdx.x;
    int lane = tid & 31, warp = tid >> 5;
    int wm = warp >> 2, wn = warp & 3;
    int gid = lane >> 2, tg = lane & 3;
    int row0 = blockIdx.y * 128, col0 = blockIdx.x * 128;
    if (DOSTAT && tid < 128) { cs[tid] = 0.0; cs2[tid] = 0.0; }

    float acc[4][4][4];
#pragma unroll
    for (int mt = 0; mt < 4; mt++)
#pragma unroll
        for (int nt = 0; nt < 4; nt++)
#pragma unroll
            for (int r = 0; r < 4; r++) acc[mt][nt][r] = 0.f;

    int rowA = row0 + (tid >> 1);
    int kA = (tid & 1) * 4;
    int rowB = tid >> 5;
    int colB = (tid & 31) * 4;
    int m0 = wm * 64, n0 = wn * 32;
    int mrow = tid >> 1;
    int nk = K / 8;

    float4 av, bv;
    {
        av = *(const float4*)&A[(size_t)rowA * lda + kA];
        if (bnm) {
            int g = kA;
            av.x = fmaxf((av.x - bnm[g])     * bnr[g]     * bng[g]     + bnb[g],     0.f);
            av.y = fmaxf((av.y - bnm[g + 1]) * bnr[g + 1] * bng[g + 1] + bnb[g + 1], 0.f);
            av.z = fmaxf((av.z - bnm[g + 2]) * bnr[g + 2] * bng[g + 2] + bnb[g + 2], 0.f);
            av.w = fmaxf((av.w - bnm[g + 3]) * bnr[g + 3] * bng[g + 3] + bnb[g + 3], 0.f);
        }
        bv = *(const float4*)&B[(size_t)rowB * ldb + col0 + colB];
        uint32_t u0, u1, u2, u3;
        CVT_TF32(u0, av.x); CVT_TF32(u1, av.y); CVT_TF32(u2, av.z); CVT_TF32(u3, av.w);
        As[0][kA + 0][mrow] = u0; As[0][kA + 1][mrow] = u1;
        As[0][kA + 2][mrow] = u2; As[0][kA + 3][mrow] = u3;
        CVT_TF32(u0, bv.x); CVT_TF32(u1, bv.y); CVT_TF32(u2, bv.z); CVT_TF32(u3, bv.w);
        Bs[0][rowB][colB] = u0; Bs[0][rowB][colB + 1] = u1;
        Bs[0][rowB][colB + 2] = u2; Bs[0][rowB][colB + 3] = u3;
    }

    for (int kt = 0; kt < nk; kt++) {
        int cur = kt & 1;
        int nxt = cur ^ 1;
        bool has = (kt + 1 < nk);
        if (has) {
            int k0 = (kt + 1) * 8;
            av = *(const float4*)&A[(size_t)rowA * lda + k0 + kA];
            if (bnm) {
                int g = k0 + kA;
                av.x = fmaxf((av.x - bnm[g])     * bnr[g]     * bng[g]     + bnb[g],     0.f);
                av.y = fmaxf((av.y - bnm[g + 1]) * bnr[g + 1] * bng[g + 1] + bnb[g + 1], 0.f);
                av.z = fmaxf((av.z - bnm[g + 2]) * bnr[g + 2] * bng[g + 2] + bnb[g + 2], 0.f);
                av.w = fmaxf((av.w - bnm[g + 3]) * bnr[g + 3] * bng[g + 3] + bnb[g + 3], 0.f);
            }
            bv = *(const float4*)&B[(size_t)(k0 + rowB) * ldb + col0 + colB];
        }
        __syncthreads();
        if (has) {
            uint32_t u0, u1, u2, u3;
            CVT_TF32(u0, av.x); CVT_TF32(u1, av.y); CVT_TF32(u2, av.z); CVT_TF32(u3, av.w);
            As[nxt][kA + 0][mrow] = u0; As[nxt][kA + 1][mrow] = u1;
            As[nxt][kA + 2][mrow] = u2; As[nxt][kA + 3][mrow] = u3;
            CVT_TF32(u0, bv.x); CVT_TF32(u1, bv.y); CVT_TF32(u2, bv.z); CVT_TF32(u3, bv.w);
            Bs[nxt][rowB][colB] = u0; Bs[nxt][rowB][colB + 1] = u1;
            Bs[nxt][rowB][colB + 2] = u2; Bs[nxt][rowB][colB + 3] = u3;
        }
        uint32_t af[4][4], bf[4][2];
#pragma unroll
        for (int mt = 0; mt < 4; mt++) {
            int mb = m0 + mt * 16 + gid;
            af[mt][0] = As[cur][tg][mb];
            af[mt][1] = As[cur][tg][mb + 8];
            af[mt][2] = As[cur][tg + 4][mb];
            af[mt][3] = As[cur][tg + 4][mb + 8];
        }
#pragma unroll
        for (int nt = 0; nt < 4; nt++) {
            int nb = n0 + nt * 8 + gid;
            bf[nt][0] = Bs[cur][tg][nb];
            bf[nt][1] = Bs[cur][tg + 4][nb];
        }
#pragma unroll
        for (int mt = 0; mt < 4; mt++)
#pragma unroll
            for (int nt = 0; nt < 4; nt++)
                MMA_TF32(acc[mt][nt][0], acc[mt][nt][1], acc[mt][nt][2], acc[mt][nt][3],
                         af[mt][0], af[mt][1], af[mt][2], af[mt][3],
                         bf[nt][0], bf[nt][1]);
    }

    float colS[4][2], colS2[4][2];
#pragma unroll
    for (int nt = 0; nt < 4; nt++) { colS[nt][0] = colS[nt][1] = 0.f; colS2[nt][0] = colS2[nt][1] = 0.f; }
#pragma unroll
    for (int mt = 0; mt < 4; mt++) {
        int r = row0 + m0 + mt * 16 + gid;
#pragma unroll
        for (int nt = 0; nt < 4; nt++) {
            int c = col0 + n0 + nt * 8 + tg * 2;
            float b0 = (bias && c < Nreal)     ? bias[c]     : 0.f;
            float b1 = (bias && c + 1 < Nreal) ? bias[c + 1] : 0.f;
            float v0 = acc[mt][nt][0] + b0;
            float v1 = acc[mt][nt][1] + b1;
            float v2 = acc[mt][nt][2] + b0;
            float v3 = acc[mt][nt][3] + b1;
            float* cr0 = &C[(size_t)r * ldc];
            float* cr1 = &C[(size_t)(r + 8) * ldc];
            if (c < Nreal)     { cr0[c] = v0; cr1[c] = v2; }
            if (c + 1 < Nreal) { cr0[c + 1] = v1; cr1[c + 1] = v3; }
            if (DOSTAT) {
                colS[nt][0]  += v0 + v2;
                colS2[nt][0] += v0 * v0 + v2 * v2;
                colS[nt][1]  += v1 + v3;
                colS2[nt][1] += v1 * v1 + v3 * v3;
            }
        }
    }
    if (DOSTAT) {
#pragma unroll
        for (int nt = 0; nt < 4; nt++) {
#pragma unroll
            for (int p = 0; p < 2; p++) {
                float a = colS[nt][p], b = colS2[nt][p];
                for (int o = 16; o >= 4; o >>= 1) {
                    a += __shfl_down_sync(0xffffffffu, a, o);
                    b += __shfl_down_sync(0xffffffffu, b, o);
                }
                colS[nt][p] = a; colS2[nt][p] = b;
            }
        }
        __syncthreads();
        if (gid == 0) {
#pragma unroll
            for (int nt = 0; nt < 4; nt++) {
                int lc = n0 + nt * 8 + tg * 2;
                atomicAdd(&cs[lc],      (double)colS[nt][0]);
                atomicAdd(&cs2[lc],     (double)colS2[nt][0]);
                atomicAdd(&cs[lc + 1],  (double)colS[nt][1]);
                atomicAdd(&cs2[lc + 1], (double)colS2[nt][1]);
            }
        }
        __syncthreads();
        if (tid < 128) {
            int gc = col0 + tid;
            if (gc < Nreal) {
                atomicAdd(&d_colsum[gc],  cs[tid]);
                atomicAdd(&d_colsum2[gc], cs2[tid]);
            }
        }
    }
}

// ------------------------- edge attention: scores + softmax denominators -------------------------
__global__ void k_D1(const int* __restrict__ ei, const int* __restrict__ ntp) {
    int warp = (blockIdx.x * blockDim.x + threadIdx.x) >> 5;
    int lane = threadIdx.x & 31;
    if (warp >= TOTROWS) return;
    int i = warp;
    int s, dd, kidx;
    if (i < EE) { s = ei[i]; dd = ei[EE + i]; kidx = i >> 10; }
    else { int n = i - EE; s = n; dd = n; kidx = BB + ntp[n]; }
    const float* kadd = &d_UKall[kidx * DD];
    const float* qrow = &d_XKMQ[(size_t)s * 600 + 400];
    const float* krow = &d_XKMQ[(size_t)dd * 600];
    int h = lane >> 3, r = lane & 7;
    float p = 0.f;
#pragma unroll
    for (int j = 0; j < 4; j++) {
        int idx = r + 8 * j;
        if (idx < 25) {
            int d0 = h * 50 + idx * 2;
            float2 q2 = *(const float2*)(qrow + d0);
            float2 k2 = *(const float2*)(krow + d0);
            float2 a2 = *(const float2*)(kadd + d0);
            p += q2.x * (k2.x + a2.x) + q2.y * (k2.y + a2.y);
        }
    }
    p += __shfl_down_sync(0xffffffffu, p, 4);
    p += __shfl_down_sync(0xffffffffu, p, 2);
    p += __shfl_down_sync(0xffffffffu, p, 1);
    if (r == 0) {
        float exv = __expf(p);
        d_ex[(size_t)i * 4 + h] = exv;
        atomicAdd(&d_den[s * 4 + h], exv);
    }
}

// ------------------------- aggregation: one warp per dst node -------------------------
__global__ __launch_bounds__(256) void k_D2w(const int* __restrict__ ei,
                                             const int* __restrict__ ntp) {
    int gw = (blockIdx.x * blockDim.x + threadIdx.x) >> 5;
    int lane = threadIdx.x & 31;
    int w = threadIdx.x >> 5;
    if (gw >= NN) return;
    int n = gw;
    int beg = d_dstOff[n], end = d_dstOff[n + 1];
    __shared__ float s_al[8][16][4];
    __shared__ int s_j[8][16], s_u[8][16];
    float acc[7];
#pragma unroll
    for (int k = 0; k < 7; k++) acc[k] = 0.f;
    for (int base = beg; base < end; base += 16) {
        int cnt = min(16, end - base);
        if (lane < cnt) {
            int i = d_csr[base + lane];
            int s, j, u;
            if (i < EE) { s = ei[i]; j = s; u = i >> 10; }
            else { int nn2 = i - EE; s = nn2; j = nn2; u = BB + ntp[nn2]; }
            s_j[w][lane] = j;
            s_u[w][lane] = u;
            float csf = (float)d_cntSrc[s];
#pragma unroll
            for (int hh = 0; hh < 4; hh++)
                s_al[w][lane][hh] = __fdividef(d_ex[(size_t)i * 4 + hh], d_den[s * 4 + hh]) * csf;
        }
        __syncwarp();
        for (int r = 0; r < cnt; r++) {
            const float* mrow = &d_XKMQ[(size_t)s_j[w][r] * 600 + 200];
            const float* urow = &d_UMall[s_u[w][r] * DD];
            float a0 = s_al[w][r][0], a1 = s_al[w][r][1];
            float a2 = s_al[w][r][2], a3 = s_al[w][r][3];
#pragma unroll
            for (int k = 0; k < 7; k++) {
                int c = lane + 32 * k;
                if (c < DD) {
                    float al = c < 50 ? a0 : c < 100 ? a1 : c < 150 ? a2 : a3;
                    acc[k] += al * (mrow[c] + urow[c]);
                }
            }
        }
        __syncwarp();
    }
#pragma unroll
    for (int k = 0; k < 7; k++) {
        int c = lane + 32 * k;
        if (c < DD) d_aggr[(size_t)n * DD + c] = acc[k];
    }
}

__global__ void k_stat3() {
    int d = threadIdx.x;
    if (d >= DD) return;
    double m = d_colsum[d] / (double)NN;
    double var = d_colsum2[d] / (double)NN - m * m;
    d_bn3m[d] = (float)m;
    d_bn3r[d] = rsqrtf((float)var + 1e-5f);
}

// ------------------------- launch (forked graph: 4-way overlap) -------------------------
extern "C" void kernel_launch(void* const* d_in, const int* in_sizes, int n_in,
                              void* d_out, int out_size) {
    const float* x    = (const float*)d_in[0];
    const float* sent = (const float*)d_in[2];
    const float* We1  = (const float*)d_in[3];
    const float* be1  = (const float*)d_in[4];
    const float* ge1  = (const float*)d_in[5];
    const float* bte1 = (const float*)d_in[6];
    const float* We2  = (const float*)d_in[7];
    const float* be2  = (const float*)d_in[8];
    const float* Wa1  = (const float*)d_in[9];
    const float* ba1  = (const float*)d_in[10];
    const float* ga1  = (const float*)d_in[11];
    const float* bta1 = (const float*)d_in[12];
    const float* Wa2  = (const float*)d_in[13];
    const float* ba2  = (const float*)d_in[14];
    const float* Watt = (const float*)d_in[15];
    const float* Wk   = (const float*)d_in[16];
    const float* bk   = (const float*)d_in[17];
    const float* Wm   = (const float*)d_in[18];
    const float* bm   = (const float*)d_in[19];
    const float* Wq   = (const float*)d_in[20];
    const float* bq   = (const float*)d_in[21];
    const float* Wo1  = (const float*)d_in[22];
    const float* bo1  = (const float*)d_in[23];
    const float* go1  = (const float*)d_in[24];
    const float* bto1 = (const float*)d_in[25];
    const float* Wo2  = (const float*)d_in[26];
    const float* bo2  = (const float*)d_in[27];
    const int* ei     = (const int*)d_in[28];
    const int* et     = (const int*)d_in[29];
    const int* ntp    = (const int*)d_in[30];
    float* out = (float*)d_out;

    void* tmp;
    cudaGetSymbolAddress(&tmp, d_Wcat);  float* pWcat = (float*)tmp;
    cudaGetSymbolAddress(&tmp, d_bcat);  float* pbcat = (float*)tmp;
    cudaGetSymbolAddress(&tmp, d_Wo1P);  float* pWo1P = (float*)tmp;
    cudaGetSymbolAddress(&tmp, d_Wo2P);  float* pWo2P = (float*)tmp;
    cudaGetSymbolAddress(&tmp, d_XKMQ);  float* pXKMQ = (float*)tmp;
    cudaGetSymbolAddress(&tmp, d_aggr);  float* pAggr = (float*)tmp;
    cudaGetSymbolAddress(&tmp, d_Y1);    float* pY1   = (float*)tmp;
    cudaGetSymbolAddress(&tmp, d_bn3m);  float* pb3m  = (float*)tmp;
    cudaGetSymbolAddress(&tmp, d_bn3r);  float* pb3r  = (float*)tmp;

    static cudaStream_t sA = nullptr, sB = nullptr, sC = nullptr;
    static cudaEvent_t evStart = nullptr, evH = nullptr, evA = nullptr, evB = nullptr, evC = nullptr;
    if (!sA) {
        cudaStreamCreateWithFlags(&sA, cudaStreamNonBlocking);
        cudaStreamCreateWithFlags(&sB, cudaStreamNonBlocking);
        cudaStreamCreateWithFlags(&sC, cudaStreamNonBlocking);
        cudaEventCreateWithFlags(&evStart, cudaEventDisableTiming);
        cudaEventCreateWithFlags(&evH, cudaEventDisableTiming);
        cudaEventCreateWithFlags(&evA, cudaEventDisableTiming);
        cudaEventCreateWithFlags(&evB, cudaEventDisableTiming);
        cudaEventCreateWithFlags(&evC, cudaEventDisableTiming);
    }

    // Fork branch A at graph root: pack weights + big XKMQ GEMM (independent of everything else).
    cudaEventRecord(evStart, 0);
    cudaStreamWaitEvent(sA, evStart, 0);
    k_pack<<<(DD * 640 + 2 * DD * 256 + 640 + 255) / 256, 256, 0, sA>>>(Wk, Wm, Wq, bk, bm, bq, Wo1, Wo2);
    {   // XKMQ = x @ [Wk1|Wm1|Wq*invs] + [bk|bm|bq*invs]
        dim3 g(5, NN / 128);
        k_gemmT<0><<<g, 256, 0, sA>>>(NN, 600, DD, x, DD, pWcat, 640, pXKMQ, 600,
                                      pbcat, nullptr, nullptr, nullptr, nullptr);
    }
    cudaEventRecord(evA, sA);

    // Main stream: zero + edge histogram.
    k_zero<<<1024, 256>>>(ntp);
    k_edgehist<<<EE / 1024, 256>>>(ei, et, ntp);
    cudaEventRecord(evH, 0);

    // Fork branch B after edgehist: CSR build.
    cudaStreamWaitEvent(sB, evH, 0);
    k_scanA<<<50, 1024, 0, sB>>>();
    k_scanB<<<1, 64, 0, sB>>>();
    k_scanC<<<50, 1024, 0, sB>>>();
    k_csrfill<<<(TOTROWS + 255) / 256, 256, 0, sB>>>(ei);
    cudaEventRecord(evB, sB);

    // Fork branch C after edgehist: combo tables + BN1 + emb (independent of segsum).
    cudaStreamWaitEvent(sC, evH, 0);
    k_tables<<<NCOMBO + NTY, 256, 0, sC>>>(We1, be1);
    k_bnstat1p<<<DD, 128, 0, sC>>>();
    k_emb<<<NCOMBO + NTY, 256, 0, sC>>>(We2, be2, ge1, bte1);
    cudaEventRecord(evC, sC);

    // Main stream: segment sums (overlaps with A, B, C).
    k_segsum3<<<400, 128>>>(x);
    k_meanT<<<(NT1 * DD + 255) / 256, 256>>>();

    // Join C (embE/embS ready), then rest of the table chain.
    cudaStreamWaitEvent(0, evC, 0);
    k_h2pre<<<NCOMBO, 256>>>(Wa1, ba1);
    k_bnstat2p<<<DD, 128>>>();
    k_Rtab<<<NCOMBO, 256>>>(Wa2, ba2, ga1, bta1);
    k_attn<<<BB, 256>>>(sent, Watt);
    k_ukum<<<BB + NTY, 256>>>(Wk, Wm);

    // Join A (XKMQ ready) before D1; join B (CSR ready) before D2.
    cudaStreamWaitEvent(0, evA, 0);
    k_D1<<<(TOTROWS + 7) / 8, 256>>>(ei, ntp);
    cudaStreamWaitEvent(0, evB, 0);
    k_D2w<<<NN / 8, 256>>>(ei, ntp);
    {   // Y1 = aggr @ Wo1 + bo1  (+ fused fp64 column stats)
        dim3 g(2, NN / 128);
        k_gemmT<1><<<g, 256>>>(NN, DD, DD, pAggr, DD, pWo1P, 256, pY1, DD,
                               bo1, nullptr, nullptr, nullptr, nullptr);
    }
    k_stat3<<<1, 256>>>();
    {   // out = relu(bn(Y1)) @ Wo2 + bo2
        dim3 g(2, NN / 128);
        k_gemmT<0><<<g, 256>>>(NN, DD, DD, pY1, DD, pWo2P, 256, out, DD,
                               bo2, pb3m, pb3r, go1, bto1);
    }
}

// round 16
// speedup vs baseline: 1.0135x; 1.0024x over previous
#include <cuda_runtime.h>
#include <math.h>
#include <stdint.h>

#define DD 200
#define NTY 4
#define NET 38
#define NT1 39
#define BB 256
#define LL 1024
#define EE 262144
#define NN 51200
#define NCOMBO 608
#define TOTROWS (EE + NN)
#define NSEG 400

// f32x2 packed-math helpers
#define FMA2(d,a,b)  asm("fma.rn.f32x2 %0, %1, %2, %3;" : "=l"(d) : "l"(a), "l"(b), "l"(d))
#define PACK2(d,x,y) asm("mov.b64 %0, {%1, %2};" : "=l"(d) : "f"(x), "f"(y))
#define UNPACK2(x,y,d) asm("mov.b64 {%0, %1}, %2;" : "=f"(x), "=f"(y) : "l"(d))

#define CVT_TF32(u,f) asm("cvt.rna.tf32.f32 %0, %1;" : "=r"(u) : "f"(f))
#define MMA_TF32(c0,c1,c2,c3,a0,a1,a2,a3,b0,b1) \
  asm("mma.sync.aligned.m16n8k8.row.col.f32.tf32.tf32.f32 " \
      "{%0,%1,%2,%3},{%4,%5,%6,%7},{%8,%9},{%0,%1,%2,%3};" \
      : "+f"(c0),"+f"(c1),"+f"(c2),"+f"(c3) \
      : "r"(a0),"r"(a1),"r"(a2),"r"(a3),"r"(b0),"r"(b1))

// ------------------------- scratch -------------------------
__device__ float d_coeff[(size_t)NN * NT1];
__device__ float d_part[(size_t)NSEG * NT1 * DD];   // per-block segment-sum partials
__device__ int   d_cntT[NT1];
__device__ int   d_cntE[NCOMBO];
__device__ int   d_cntN[NTY];
__device__ int   d_combo[EE];
__device__ int   d_cntSrc[NN];
__device__ int   d_dstCnt[NN];
__device__ int   d_dstOff[NN + 1];
__device__ int   d_cursor[NN];
__device__ int   d_csr[TOTROWS];
__device__ int   d_blkSum[50];
__device__ float d_meanT[NT1 * DD];
__device__ float d_preE[NCOMBO * DD];
__device__ float d_preS[NTY * DD];
__device__ float d_embE[NCOMBO * DD];
__device__ float d_embS[NTY * DD];
__device__ float d_h2[NCOMBO * DD];
__device__ float d_Rtab[NCOMBO * DD];
__device__ float d_bn1m[DD], d_bn1r[DD], d_bn2m[DD], d_bn2r[DD], d_bn3m[DD], d_bn3r[DD];
__device__ float d_upd[BB * DD];
__device__ float d_UKall[(BB + NTY) * DD];
__device__ float d_UMall[(BB + NTY) * DD];
__device__ float d_Wcat[DD * 640];
__device__ float d_bcat[640];
__device__ float d_Wo1P[DD * 256];
__device__ float d_Wo2P[DD * 256];
__device__ float d_XKMQ[(size_t)NN * 600];    // per-node [XK+bk | XM+bm | (XQ+bq)*invs]
__device__ float d_ex[(size_t)TOTROWS * 4];
__device__ float d_den[NN * 4];
__device__ float d_aggr[(size_t)NN * DD];
__device__ float d_Y1[(size_t)NN * DD];
__device__ double d_colsum[DD], d_colsum2[DD];   // fp64 BN3 stats

// ------------------------- zero init + node hist (fused) -------------------------
__global__ void k_zero(const int* __restrict__ ntp) {
    long long i0 = (long long)blockIdx.x * blockDim.x + threadIdx.x;
    long long st = (long long)gridDim.x * blockDim.x;
    for (long long i = i0; i < (long long)NT1 * NN; i += st) d_coeff[i] = 0.f;
    for (long long i = i0; i < (long long)NN * 4; i += st) d_den[i] = 0.f;
    for (long long i = i0; i < NCOMBO; i += st) d_cntE[i] = 0;
    for (long long i = i0; i < NT1; i += st) d_cntT[i] = 0;
    for (long long i = i0; i < NTY; i += st) d_cntN[i] = 0;
    for (long long i = i0; i < DD; i += st) { d_colsum[i] = 0.0; d_colsum2[i] = 0.0; }
    for (long long i = i0; i < NN; i += st) {
        d_cntSrc[i] = 1;
        d_dstCnt[i] = 1;
        atomicAdd(&d_cntN[ntp[i]], 1);
    }
}

// smem histograms + 4 edges/thread for atomic-chain ILP
__global__ void k_edgehist(const int* __restrict__ ei, const int* __restrict__ et,
                           const int* __restrict__ ntp) {
    __shared__ int sT[NT1];
    __shared__ int sE[NCOMBO];
    int tid = threadIdx.x;
    for (int i = tid; i < NT1; i += 256) sT[i] = 0;
    for (int i = tid; i < NCOMBO; i += 256) sE[i] = 0;
    __syncthreads();
    int e0 = blockIdx.x * 1024 + tid;
    int s[4], dd[4], t[4];
#pragma unroll
    for (int j = 0; j < 4; j++) {
        int e = e0 + j * 256;
        s[j]  = ei[e];
        dd[j] = ei[EE + e];
        t[j]  = et[e];
    }
#pragma unroll
    for (int j = 0; j < 4; j++)
        atomicAdd(&d_coeff[(size_t)dd[j] * NT1 + t[j]], 1.f);
#pragma unroll
    for (int j = 0; j < 4; j++)
        atomicAdd(&d_coeff[(size_t)s[j] * NT1 + t[j]], -1.f);
#pragma unroll
    for (int j = 0; j < 4; j++) {
        int e = e0 + j * 256;
        atomicAdd(&sT[t[j]], 1);
        int c = (t[j] << 4) | (ntp[s[j]] << 2) | ntp[dd[j]];
        d_combo[e] = c;
        atomicAdd(&sE[c], 1);
    }
#pragma unroll
    for (int j = 0; j < 4; j++) atomicAdd(&d_cntSrc[s[j]], 1);
#pragma unroll
    for (int j = 0; j < 4; j++) atomicAdd(&d_dstCnt[dd[j]], 1);
    __syncthreads();
    for (int i = tid; i < NT1; i += 256) if (sT[i]) atomicAdd(&d_cntT[i], sT[i]);
    for (int i = tid; i < NCOMBO; i += 256) if (sE[i]) atomicAdd(&d_cntE[i], sE[i]);
}

// ------------------------- dst-CSR build (3-phase parallel scan) -------------------------
__global__ void k_scanA() {
    __shared__ int sm[1024];
    int tid = threadIdx.x;
    sm[tid] = d_dstCnt[blockIdx.x * 1024 + tid];
    __syncthreads();
    for (int o = 512; o > 0; o >>= 1) {
        if (tid < o) sm[tid] += sm[tid + o];
        __syncthreads();
    }
    if (tid == 0) d_blkSum[blockIdx.x] = sm[0];
}

__global__ void k_scanB() {
    __shared__ int sm[64];
    int tid = threadIdx.x;
    int v = (tid < 50) ? d_blkSum[tid] : 0;
    sm[tid] = v;
    __syncthreads();
    for (int o = 1; o < 64; o <<= 1) {
        int t = (tid >= o) ? sm[tid - o] : 0;
        __syncthreads();
        sm[tid] += t;
        __syncthreads();
    }
    if (tid < 50) d_blkSum[tid] = sm[tid] - v;
    if (tid == 49) d_dstOff[NN] = sm[49];
}

__global__ void k_scanC() {
    __shared__ int sm[1024];
    int tid = threadIdx.x;
    int g = blockIdx.x * 1024 + tid;
    int v = d_dstCnt[g];
    sm[tid] = v;
    __syncthreads();
    for (int o = 1; o < 1024; o <<= 1) {
        int t = (tid >= o) ? sm[tid - o] : 0;
        __syncthreads();
        sm[tid] += t;
        __syncthreads();
    }
    int excl = sm[tid] - v + d_blkSum[blockIdx.x];
    d_dstOff[g] = excl;
    d_cursor[g] = excl;
}

__global__ void k_csrfill(const int* __restrict__ ei) {
    int i = blockIdx.x * blockDim.x + threadIdx.x;
    if (i >= TOTROWS) return;
    int dst = (i < EE) ? ei[EE + i] : (i - EE);
    int pos = atomicAdd(&d_cursor[dst], 1);
    d_csr[pos] = i;
}

// sort each node's CSR segment by edge index -> deterministic D2 accumulation order
__global__ void k_csrsort() {
    int n = blockIdx.x * blockDim.x + threadIdx.x;
    if (n >= NN) return;
    int beg = d_dstOff[n], end = d_dstOff[n + 1];
    for (int i = beg + 1; i < end; i++) {
        int v = d_csr[i];
        int j = i - 1;
        while (j >= beg && d_csr[j] > v) { d_csr[j + 1] = d_csr[j]; j--; }
        d_csr[j + 1] = v;
    }
}

// ------------------------- segment sums (deterministic: partials + fixed-order reduce) ----
__global__ __launch_bounds__(128) void k_segsum3(const float* __restrict__ x) {
    __shared__ unsigned long long cf2[128][NT1];
    int tid = threadIdx.x;
    int n0 = blockIdx.x * 128;
    for (int i = tid; i < 128 * NT1; i += 128) {
        float c = d_coeff[(size_t)(n0 + i / NT1) * NT1 + (i % NT1)];
        unsigned long long c2; PACK2(c2, c, c);
        cf2[i / NT1][i % NT1] = c2;
    }
    __syncthreads();
    if (tid < 100) {
        unsigned long long acc[NT1];
#pragma unroll
        for (int t = 0; t < NT1; t++) acc[t] = 0ULL;
        for (int nn = 0; nn < 128; nn++) {
            float2 xv = *(const float2*)&x[(size_t)(n0 + nn) * DD + tid * 2];
            unsigned long long xv2; PACK2(xv2, xv.x, xv.y);
#pragma unroll
            for (int t = 0; t < NT1; t++)
                FMA2(acc[t], cf2[nn][t], xv2);
        }
        float* dst = &d_part[(size_t)blockIdx.x * (NT1 * DD)];
#pragma unroll
        for (int t = 0; t < NT1; t++) {
            float lo, hi; UNPACK2(lo, hi, acc[t]);
            dst[t * DD + tid * 2]     = lo;
            dst[t * DD + tid * 2 + 1] = hi;
        }
    }
}

// fixed-order reduction over the 400 partials, fused with meanT
__global__ void k_segred() {
    int i = blockIdx.x * 256 + threadIdx.x;
    if (i >= NT1 * DD) return;
    float s = 0.f;
    for (int b = 0; b < NSEG; b++)
        s += d_part[(size_t)b * (NT1 * DD) + i];
    int t = i / DD;
    float c = (float)d_cntT[t];
    if (c < 1.f) c = 1.f;
    d_meanT[i] = s / c;
}

// ------------------------- combo tables -------------------------
__global__ void k_tables(const float* __restrict__ We1, const float* __restrict__ be1) {
    int c = blockIdx.x, d = threadIdx.x;
    if (d >= DD) return;
    if (c < NCOMBO) {
        int t = c >> 4, a = (c >> 2) & 3, b = c & 3;
        d_preE[c * DD + d] = We1[t * DD + d] + We1[(NT1 + a) * DD + d]
                           + We1[(NT1 + NTY + b) * DD + d] + be1[d];
    } else {
        int t = c - NCOMBO;
        d_preS[t * DD + d] = We1[NET * DD + d] + We1[(NT1 + t) * DD + d]
                           + We1[(NT1 + NTY + t) * DD + d] + be1[d];
    }
}

__global__ void k_bnstat1p() {
    int d = blockIdx.x, tid = threadIdx.x;
    __shared__ double rs[128], rs2[128];
    double s = 0.0, s2 = 0.0;
    for (int c = tid; c < NCOMBO; c += 128) {
        double w = (double)d_cntE[c], v = (double)d_preE[c * DD + d];
        s += w * v; s2 += w * v * v;
    }
    if (tid < NTY) {
        double w = (double)d_cntN[tid], v = (double)d_preS[tid * DD + d];
        s += w * v; s2 += w * v * v;
    }
    rs[tid] = s; rs2[tid] = s2;
    __syncthreads();
    for (int o = 64; o > 0; o >>= 1) {
        if (tid < o) { rs[tid] += rs[tid + o]; rs2[tid] += rs2[tid + o]; }
        __syncthreads();
    }
    if (tid == 0) {
        double m = rs[0] / (double)TOTROWS;
        double var = rs2[0] / (double)TOTROWS - m * m;
        d_bn1m[d] = (float)m;
        d_bn1r[d] = rsqrtf((float)var + 1e-5f);
    }
}

__global__ void k_emb(const float* __restrict__ We2, const float* __restrict__ be2,
                      const float* __restrict__ g, const float* __restrict__ bt) {
    int c = blockIdx.x, d = threadIdx.x;
    __shared__ float a[DD];
    const float* srow = (c < NCOMBO) ? &d_preE[c * DD] : &d_preS[(c - NCOMBO) * DD];
    if (d < DD) {
        float v = (srow[d] - d_bn1m[d]) * d_bn1r[d] * g[d] + bt[d];
        a[d] = fmaxf(v, 0.f);
    }
    __syncthreads();
    if (d < DD) {
        float acc = 0.f;
        for (int k = 0; k < DD; k++) acc += a[k] * We2[k * DD + d];
        float* dst = (c < NCOMBO) ? &d_embE[c * DD] : &d_embS[(c - NCOMBO) * DD];
        dst[d] = acc + be2[d];
    }
}

__global__ void k_h2pre(const float* __restrict__ Wa1, const float* __restrict__ ba1) {
    int c = blockIdx.x, d = threadIdx.x;
    __shared__ float e[DD], mt[DD];
    int t = c >> 4;
    if (d < DD) { e[d] = d_embE[c * DD + d]; mt[d] = d_meanT[t * DD + d]; }
    __syncthreads();
    if (d < DD) {
        float acc = ba1[d];
        for (int k = 0; k < DD; k++) acc += e[k] * Wa1[k * DD + d];
        for (int k = 0; k < DD; k++) acc += mt[k] * Wa1[(DD + k) * DD + d];
        d_h2[c * DD + d] = acc;
    }
}

__global__ void k_bnstat2p() {
    int d = blockIdx.x, tid = threadIdx.x;
    __shared__ double rs[128], rs2[128];
    double s = 0.0, s2 = 0.0;
    for (int c = tid; c < NCOMBO; c += 128) {
        double w = (double)d_cntE[c], v = (double)d_h2[c * DD + d];
        s += w * v; s2 += w * v * v;
    }
    rs[tid] = s; rs2[tid] = s2;
    __syncthreads();
    for (int o = 64; o > 0; o >>= 1) {
        if (tid < o) { rs[tid] += rs[tid + o]; rs2[tid] += rs2[tid + o]; }
        __syncthreads();
    }
    if (tid == 0) {
        double m = rs[0] / (double)EE;
        double var = rs2[0] / (double)EE - m * m;
        d_bn2m[d] = (float)m;
        d_bn2r[d] = rsqrtf((float)var + 1e-5f);
    }
}

__global__ void k_Rtab(const float* __restrict__ Wa2, const float* __restrict__ ba2,
                       const float* __restrict__ g, const float* __restrict__ bt) {
    int c = blockIdx.x, d = threadIdx.x;
    __shared__ float a[DD];
    if (d < DD) {
        float v = (d_h2[c * DD + d] - d_bn2m[d]) * d_bn2r[d] * g[d] + bt[d];
        a[d] = fmaxf(v, 0.f);
    }
    __syncthreads();
    if (d < DD) {
        float acc = 0.f;
        for (int k = 0; k < DD; k++) acc += a[k] * Wa2[k * DD + d];
        d_Rtab[c * DD + d] = acc + ba2[d];
    }
}

// ------------------------- fused graph attention -------------------------
__global__ __launch_bounds__(256) void k_attn(const float* __restrict__ sent,
                                              const float* __restrict__ Watt) {
    int b = blockIdx.x, tid = threadIdx.x;
    __shared__ float sv[DD], q[DD];
    __shared__ float Pb[NCOMBO], Wacc[NCOMBO];
    __shared__ float red[256];
    if (tid < DD) sv[tid] = sent[b * DD + tid];
    for (int i = tid; i < NCOMBO; i += 256) Wacc[i] = 0.f;
    __syncthreads();
    if (tid < DD) {
        float a = 0.f;
        for (int k = 0; k < DD; k++) a += sv[k] * Watt[k * DD + tid];
        q[tid] = a * 0.07071067811865475f;   // 1/sqrt(200)
    }
    __syncthreads();
    int lane = tid & 31, w = tid >> 5;
    for (int c = w; c < NCOMBO; c += 8) {
        float p = 0.f;
        for (int k = lane; k < DD; k += 32) p += q[k] * d_Rtab[c * DD + k];
        for (int o = 16; o > 0; o >>= 1) p += __shfl_down_sync(0xffffffffu, p, o);
        if (lane == 0) Pb[c] = p;
    }
    __syncthreads();
    int cid[4]; float sc[4]; float lmax = -1e30f;
#pragma unroll
    for (int j = 0; j < 4; j++) {
        int e = b * LL + tid + j * 256;
        cid[j] = d_combo[e];
        sc[j] = Pb[cid[j]];
        lmax = fmaxf(lmax, sc[j]);
    }
    red[tid] = lmax; __syncthreads();
    for (int s = 128; s > 0; s >>= 1) { if (tid < s) red[tid] = fmaxf(red[tid], red[tid + s]); __syncthreads(); }
    float bmax = red[0]; __syncthreads();
    float lsum = 0.f;
#pragma unroll
    for (int j = 0; j < 4; j++) { sc[j] = expf(sc[j] - bmax); lsum += sc[j]; }
    red[tid] = lsum; __syncthreads();
    for (int s = 128; s > 0; s >>= 1) { if (tid < s) red[tid] += red[tid + s]; __syncthreads(); }
    float inv = 1.f / red[0]; __syncthreads();
#pragma unroll
    for (int j = 0; j < 4; j++) atomicAdd(&Wacc[cid[j]], sc[j] * inv);
    __syncthreads();
    if (tid < DD) {
        float a = 0.f;
        for (int c = 0; c < NCOMBO; c++) a += Wacc[c] * d_Rtab[c * DD + tid];
        d_upd[b * DD + tid] = a;
    }
}

__global__ void k_ukum(const float* __restrict__ Wk, const float* __restrict__ Wm) {
    int id = blockIdx.x, d = threadIdx.x;
    __shared__ float s[DD];
    const float* srow = (id < BB) ? &d_upd[id * DD] : &d_embS[(id - BB) * DD];
    if (d < DD) s[d] = srow[d];
    __syncthreads();
    if (d < DD) {
        float ak = 0.f, am = 0.f;
        for (int k = 0; k < DD; k++) {
            float sv = s[k];
            ak += sv * Wk[(DD + k) * DD + d];
            am += sv * Wm[(DD + k) * DD + d];
        }
        d_UKall[id * DD + d] = ak;
        d_UMall[id * DD + d] = am;
    }
}

// ------------------------- weight packing -------------------------
__global__ void k_pack(const float* __restrict__ Wk, const float* __restrict__ Wm,
                       const float* __restrict__ Wq,
                       const float* __restrict__ bk, const float* __restrict__ bm,
                       const float* __restrict__ bq,
                       const float* __restrict__ Wo1, const float* __restrict__ Wo2) {
    const float invs = 0.1414213562373095f;   // 1/sqrt(50)
    int i = blockIdx.x * blockDim.x + threadIdx.x;
    if (i < DD * 640) {
        int k = i / 640, c = i % 640;
        float v = (c < DD) ? Wk[k * DD + c]
                : (c < 2 * DD) ? Wm[k * DD + (c - DD)]
                : (c < 3 * DD) ? Wq[k * DD + (c - 2 * DD)] * invs : 0.f;
        d_Wcat[i] = v;
        return;
    }
    int j = i - DD * 640;
    if (j < DD * 256) {
        int k = j >> 8, c = j & 255;
        d_Wo1P[j] = (c < DD) ? Wo1[k * DD + c] : 0.f;
        return;
    }
    j -= DD * 256;
    if (j < DD * 256) {
        int k = j >> 8, c = j & 255;
        d_Wo2P[j] = (c < DD) ? Wo2[k * DD + c] : 0.f;
        return;
    }
    j -= DD * 256;
    if (j < 640) {
        float v = (j < DD) ? bk[j]
                : (j < 2 * DD) ? bm[j - DD]
                : (j < 3 * DD) ? bq[j - 2 * DD] * invs : 0.f;
        d_bcat[j] = v;
    }
}

// ------------------------- tf32 GEMM: 128x128 tile, 2-stage smem pipeline -------------------------
template<int DOSTAT>
__global__ __launch_bounds__(256, 2) void k_gemmT(
    int M, int Nreal, int K,
    const float* __restrict__ A, int lda,
    const float* __restrict__ B, int ldb,
    float* __restrict__ C, int ldc,
    const float* __restrict__ bias,
    const float* __restrict__ bnm, const float* __restrict__ bnr,
    const float* __restrict__ bng, const float* __restrict__ bnb) {
    __shared__ uint32_t As[2][8][132];
    __shared__ uint32_t Bs[2][8][132];
    __shared__ double cs[128], cs2[128];
    int tid = threadIdx.x;
    int lane = tid & 31, warp = tid >> 5;
    int wm = warp >> 2, wn = warp & 3;
    int gid = lane >> 2, tg = lane & 3;
    int row0 = blockIdx.y * 128, col0 = blockIdx.x * 128;
    if (DOSTAT && tid < 128) { cs[tid] = 0.0; cs2[tid] = 0.0; }

    float acc[4][4][4];
#pragma unroll
    for (int mt = 0; mt < 4; mt++)
#pragma unroll
        for (int nt = 0; nt < 4; nt++)
#pragma unroll
            for (int r = 0; r < 4; r++) acc[mt][nt][r] = 0.f;

    int rowA = row0 + (tid >> 1);
    int kA = (tid & 1) * 4;
    int rowB = tid >> 5;
    int colB = (tid & 31) * 4;
    int m0 = wm * 64, n0 = wn * 32;
    int mrow = tid >> 1;
    int nk = K / 8;

    float4 av, bv;
    {
        av = *(const float4*)&A[(size_t)rowA * lda + kA];
        if (bnm) {
            int g = kA;
            av.x = fmaxf((av.x - bnm[g])     * bnr[g]     * bng[g]     + bnb[g],     0.f);
            av.y = fmaxf((av.y - bnm[g + 1]) * bnr[g + 1] * bng[g + 1] + bnb[g + 1], 0.f);
            av.z = fmaxf((av.z - bnm[g + 2]) * bnr[g + 2] * bng[g + 2] + bnb[g + 2], 0.f);
            av.w = fmaxf((av.w - bnm[g + 3]) * bnr[g + 3] * bng[g + 3] + bnb[g + 3], 0.f);
        }
        bv = *(const float4*)&B[(size_t)rowB * ldb + col0 + colB];
        uint32_t u0, u1, u2, u3;
        CVT_TF32(u0, av.x); CVT_TF32(u1, av.y); CVT_TF32(u2, av.z); CVT_TF32(u3, av.w);
        As[0][kA + 0][mrow] = u0; As[0][kA + 1][mrow] = u1;
        As[0][kA + 2][mrow] = u2; As[0][kA + 3][mrow] = u3;
        CVT_TF32(u0, bv.x); CVT_TF32(u1, bv.y); CVT_TF32(u2, bv.z); CVT_TF32(u3, bv.w);
        Bs[0][rowB][colB] = u0; Bs[0][rowB][colB + 1] = u1;
        Bs[0][rowB][colB + 2] = u2; Bs[0][rowB][colB + 3] = u3;
    }

    for (int kt = 0; kt < nk; kt++) {
        int cur = kt & 1;
        int nxt = cur ^ 1;
        bool has = (kt + 1 < nk);
        if (has) {
            int k0 = (kt + 1) * 8;
            av = *(const float4*)&A[(size_t)rowA * lda + k0 + kA];
            if (bnm) {
                int g = k0 + kA;
                av.x = fmaxf((av.x - bnm[g])     * bnr[g]     * bng[g]     + bnb[g],     0.f);
                av.y = fmaxf((av.y - bnm[g + 1]) * bnr[g + 1] * bng[g + 1] + bnb[g + 1], 0.f);
                av.z = fmaxf((av.z - bnm[g + 2]) * bnr[g + 2] * bng[g + 2] + bnb[g + 2], 0.f);
                av.w = fmaxf((av.w - bnm[g + 3]) * bnr[g + 3] * bng[g + 3] + bnb[g + 3], 0.f);
            }
            bv = *(const float4*)&B[(size_t)(k0 + rowB) * ldb + col0 + colB];
        }
        __syncthreads();
        if (has) {
            uint32_t u0, u1, u2, u3;
            CVT_TF32(u0, av.x); CVT_TF32(u1, av.y); CVT_TF32(u2, av.z); CVT_TF32(u3, av.w);
            As[nxt][kA + 0][mrow] = u0; As[nxt][kA + 1][mrow] = u1;
            As[nxt][kA + 2][mrow] = u2; As[nxt][kA + 3][mrow] = u3;
            CVT_TF32(u0, bv.x); CVT_TF32(u1, bv.y); CVT_TF32(u2, bv.z); CVT_TF32(u3, bv.w);
            Bs[nxt][rowB][colB] = u0; Bs[nxt][rowB][colB + 1] = u1;
            Bs[nxt][rowB][colB + 2] = u2; Bs[nxt][rowB][colB + 3] = u3;
        }
        uint32_t af[4][4], bf[4][2];
#pragma unroll
        for (int mt = 0; mt < 4; mt++) {
            int mb = m0 + mt * 16 + gid;
            af[mt][0] = As[cur][tg][mb];
            af[mt][1] = As[cur][tg][mb + 8];
            af[mt][2] = As[cur][tg + 4][mb];
            af[mt][3] = As[cur][tg + 4][mb + 8];
        }
#pragma unroll
        for (int nt = 0; nt < 4; nt++) {
            int nb = n0 + nt * 8 + gid;
            bf[nt][0] = Bs[cur][tg][nb];
            bf[nt][1] = Bs[cur][tg + 4][nb];
        }
#pragma unroll
        for (int mt = 0; mt < 4; mt++)
#pragma unroll
            for (int nt = 0; nt < 4; nt++)
                MMA_TF32(acc[mt][nt][0], acc[mt][nt][1], acc[mt][nt][2], acc[mt][nt][3],
                         af[mt][0], af[mt][1], af[mt][2], af[mt][3],
                         bf[nt][0], bf[nt][1]);
    }

    float colS[4][2], colS2[4][2];
#pragma unroll
    for (int nt = 0; nt < 4; nt++) { colS[nt][0] = colS[nt][1] = 0.f; colS2[nt][0] = colS2[nt][1] = 0.f; }
#pragma unroll
    for (int mt = 0; mt < 4; mt++) {
        int r = row0 + m0 + mt * 16 + gid;
#pragma unroll
        for (int nt = 0; nt < 4; nt++) {
            int c = col0 + n0 + nt * 8 + tg * 2;
            float b0 = (bias && c < Nreal)     ? bias[c]     : 0.f;
            float b1 = (bias && c + 1 < Nreal) ? bias[c + 1] : 0.f;
            float v0 = acc[mt][nt][0] + b0;
            float v1 = acc[mt][nt][1] + b1;
            float v2 = acc[mt][nt][2] + b0;
            float v3 = acc[mt][nt][3] + b1;
            float* cr0 = &C[(size_t)r * ldc];
            float* cr1 = &C[(size_t)(r + 8) * ldc];
            if (c < Nreal)     { cr0[c] = v0; cr1[c] = v2; }
            if (c + 1 < Nreal) { cr0[c + 1] = v1; cr1[c + 1] = v3; }
            if (DOSTAT) {
                colS[nt][0]  += v0 + v2;
                colS2[nt][0] += v0 * v0 + v2 * v2;
                colS[nt][1]  += v1 + v3;
                colS2[nt][1] += v1 * v1 + v3 * v3;
            }
        }
    }
    if (DOSTAT) {
#pragma unroll
        for (int nt = 0; nt < 4; nt++) {
#pragma unroll
            for (int p = 0; p < 2; p++) {
                float a = colS[nt][p], b = colS2[nt][p];
                for (int o = 16; o >= 4; o >>= 1) {
                    a += __shfl_down_sync(0xffffffffu, a, o);
                    b += __shfl_down_sync(0xffffffffu, b, o);
                }
                colS[nt][p] = a; colS2[nt][p] = b;
            }
        }
        __syncthreads();
        if (gid == 0) {
#pragma unroll
            for (int nt = 0; nt < 4; nt++) {
                int lc = n0 + nt * 8 + tg * 2;
                atomicAdd(&cs[lc],      (double)colS[nt][0]);
                atomicAdd(&cs2[lc],     (double)colS2[nt][0]);
                atomicAdd(&cs[lc + 1],  (double)colS[nt][1]);
                atomicAdd(&cs2[lc + 1], (double)colS2[nt][1]);
            }
        }
        __syncthreads();
        if (tid < 128) {
            int gc = col0 + tid;
            if (gc < Nreal) {
                atomicAdd(&d_colsum[gc],  cs[tid]);
                atomicAdd(&d_colsum2[gc], cs2[tid]);
            }
        }
    }
}

// ------------------------- edge attention: scores + softmax denominators -------------------------
__global__ void k_D1(const int* __restrict__ ei, const int* __restrict__ ntp) {
    int warp = (blockIdx.x * blockDim.x + threadIdx.x) >> 5;
    int lane = threadIdx.x & 31;
    if (warp >= TOTROWS) return;
    int i = warp;
    int s, dd, kidx;
    if (i < EE) { s = ei[i]; dd = ei[EE + i]; kidx = i >> 10; }
    else { int n = i - EE; s = n; dd = n; kidx = BB + ntp[n]; }
    const float* kadd = &d_UKall[kidx * DD];
    const float* qrow = &d_XKMQ[(size_t)s * 600 + 400];
    const float* krow = &d_XKMQ[(size_t)dd * 600];
    int h = lane >> 3, r = lane & 7;
    float p = 0.f;
#pragma unroll
    for (int j = 0; j < 4; j++) {
        int idx = r + 8 * j;
        if (idx < 25) {
            int d0 = h * 50 + idx * 2;
            float2 q2 = *(const float2*)(qrow + d0);
            float2 k2 = *(const float2*)(krow + d0);
            float2 a2 = *(const float2*)(kadd + d0);
            p += q2.x * (k2.x + a2.x) + q2.y * (k2.y + a2.y);
        }
    }
    p += __shfl_down_sync(0xffffffffu, p, 4);
    p += __shfl_down_sync(0xffffffffu, p, 2);
    p += __shfl_down_sync(0xffffffffu, p, 1);
    if (r == 0) {
        float exv = __expf(p);
        d_ex[(size_t)i * 4 + h] = exv;
        atomicAdd(&d_den[s * 4 + h], exv);
    }
}

// ------------------------- aggregation: one warp per dst node (sorted CSR => deterministic) ----
__global__ __launch_bounds__(256) void k_D2w(const int* __restrict__ ei,
                                             const int* __restrict__ ntp) {
    int gw = (blockIdx.x * blockDim.x + threadIdx.x) >> 5;
    int lane = threadIdx.x & 31;
    int w = threadIdx.x >> 5;
    if (gw >= NN) return;
    int n = gw;
    int beg = d_dstOff[n], end = d_dstOff[n + 1];
    __shared__ float s_al[8][16][4];
    __shared__ int s_j[8][16], s_u[8][16];
    float acc[7];
#pragma unroll
    for (int k = 0; k < 7; k++) acc[k] = 0.f;
    for (int base = beg; base < end; base += 16) {
        int cnt = min(16, end - base);
        if (lane < cnt) {
            int i = d_csr[base + lane];
            int s, j, u;
            if (i < EE) { s = ei[i]; j = s; u = i >> 10; }
            else { int nn2 = i - EE; s = nn2; j = nn2; u = BB + ntp[nn2]; }
            s_j[w][lane] = j;
            s_u[w][lane] = u;
            float csf = (float)d_cntSrc[s];
#pragma unroll
            for (int hh = 0; hh < 4; hh++)
                s_al[w][lane][hh] = __fdividef(d_ex[(size_t)i * 4 + hh], d_den[s * 4 + hh]) * csf;
        }
        __syncwarp();
        for (int r = 0; r < cnt; r++) {
            const float* mrow = &d_XKMQ[(size_t)s_j[w][r] * 600 + 200];
            const float* urow = &d_UMall[s_u[w][r] * DD];
            float a0 = s_al[w][r][0], a1 = s_al[w][r][1];
            float a2 = s_al[w][r][2], a3 = s_al[w][r][3];
#pragma unroll
            for (int k = 0; k < 7; k++) {
                int c = lane + 32 * k;
                if (c < DD) {
                    float al = c < 50 ? a0 : c < 100 ? a1 : c < 150 ? a2 : a3;
                    acc[k] += al * (mrow[c] + urow[c]);
                }
            }
        }
        __syncwarp();
    }
#pragma unroll
    for (int k = 0; k < 7; k++) {
        int c = lane + 32 * k;
        if (c < DD) d_aggr[(size_t)n * DD + c] = acc[k];
    }
}

__global__ void k_stat3() {
    int d = threadIdx.x;
    if (d >= DD) return;
    double m = d_colsum[d] / (double)NN;
    double var = d_colsum2[d] / (double)NN - m * m;
    d_bn3m[d] = (float)m;
    d_bn3r[d] = rsqrtf((float)var + 1e-5f);
}

// ------------------------- launch (forked graph: 4-way overlap) -------------------------
extern "C" void kernel_launch(void* const* d_in, const int* in_sizes, int n_in,
                              void* d_out, int out_size) {
    const float* x    = (const float*)d_in[0];
    const float* sent = (const float*)d_in[2];
    const float* We1  = (const float*)d_in[3];
    const float* be1  = (const float*)d_in[4];
    const float* ge1  = (const float*)d_in[5];
    const float* bte1 = (const float*)d_in[6];
    const float* We2  = (const float*)d_in[7];
    const float* be2  = (const float*)d_in[8];
    const float* Wa1  = (const float*)d_in[9];
    const float* ba1  = (const float*)d_in[10];
    const float* ga1  = (const float*)d_in[11];
    const float* bta1 = (const float*)d_in[12];
    const float* Wa2  = (const float*)d_in[13];
    const float* ba2  = (const float*)d_in[14];
    const float* Watt = (const float*)d_in[15];
    const float* Wk   = (const float*)d_in[16];
    const float* bk   = (const float*)d_in[17];
    const float* Wm   = (const float*)d_in[18];
    const float* bm   = (const float*)d_in[19];
    const float* Wq   = (const float*)d_in[20];
    const float* bq   = (const float*)d_in[21];
    const float* Wo1  = (const float*)d_in[22];
    const float* bo1  = (const float*)d_in[23];
    const float* go1  = (const float*)d_in[24];
    const float* bto1 = (const float*)d_in[25];
    const float* Wo2  = (const float*)d_in[26];
    const float* bo2  = (const float*)d_in[27];
    const int* ei     = (const int*)d_in[28];
    const int* et     = (const int*)d_in[29];
    const int* ntp    = (const int*)d_in[30];
    float* out = (float*)d_out;

    void* tmp;
    cudaGetSymbolAddress(&tmp, d_Wcat);  float* pWcat = (float*)tmp;
    cudaGetSymbolAddress(&tmp, d_bcat);  float* pbcat = (float*)tmp;
    cudaGetSymbolAddress(&tmp, d_Wo1P);  float* pWo1P = (float*)tmp;
    cudaGetSymbolAddress(&tmp, d_Wo2P);  float* pWo2P = (float*)tmp;
    cudaGetSymbolAddress(&tmp, d_XKMQ);  float* pXKMQ = (float*)tmp;
    cudaGetSymbolAddress(&tmp, d_aggr);  float* pAggr = (float*)tmp;
    cudaGetSymbolAddress(&tmp, d_Y1);    float* pY1   = (float*)tmp;
    cudaGetSymbolAddress(&tmp, d_bn3m);  float* pb3m  = (float*)tmp;
    cudaGetSymbolAddress(&tmp, d_bn3r);  float* pb3r  = (float*)tmp;

    static cudaStream_t sA = nullptr, sB = nullptr, sC = nullptr;
    static cudaEvent_t evStart = nullptr, evH = nullptr, evA = nullptr, evB = nullptr, evC = nullptr;
    if (!sA) {
        cudaStreamCreateWithFlags(&sA, cudaStreamNonBlocking);
        cudaStreamCreateWithFlags(&sB, cudaStreamNonBlocking);
        cudaStreamCreateWithFlags(&sC, cudaStreamNonBlocking);
        cudaEventCreateWithFlags(&evStart, cudaEventDisableTiming);
        cudaEventCreateWithFlags(&evH, cudaEventDisableTiming);
        cudaEventCreateWithFlags(&evA, cudaEventDisableTiming);
        cudaEventCreateWithFlags(&evB, cudaEventDisableTiming);
        cudaEventCreateWithFlags(&evC, cudaEventDisableTiming);
    }

    // Fork branch A at graph root: pack weights + big XKMQ GEMM (independent of everything else).
    cudaEventRecord(evStart, 0);
    cudaStreamWaitEvent(sA, evStart, 0);
    k_pack<<<(DD * 640 + 2 * DD * 256 + 640 + 255) / 256, 256, 0, sA>>>(Wk, Wm, Wq, bk, bm, bq, Wo1, Wo2);
    {   // XKMQ = x @ [Wk1|Wm1|Wq*invs] + [bk|bm|bq*invs]
        dim3 g(5, NN / 128);
        k_gemmT<0><<<g, 256, 0, sA>>>(NN, 600, DD, x, DD, pWcat, 640, pXKMQ, 600,
                                      pbcat, nullptr, nullptr, nullptr, nullptr);
    }
    cudaEventRecord(evA, sA);

    // Main stream: zero + edge histogram.
    k_zero<<<1024, 256>>>(ntp);
    k_edgehist<<<EE / 1024, 256>>>(ei, et, ntp);
    cudaEventRecord(evH, 0);

    // Fork branch B after edgehist: CSR build + deterministic segment sort.
    cudaStreamWaitEvent(sB, evH, 0);
    k_scanA<<<50, 1024, 0, sB>>>();
    k_scanB<<<1, 64, 0, sB>>>();
    k_scanC<<<50, 1024, 0, sB>>>();
    k_csrfill<<<(TOTROWS + 255) / 256, 256, 0, sB>>>(ei);
    k_csrsort<<<NN / 256, 256, 0, sB>>>();
    cudaEventRecord(evB, sB);

    // Fork branch C after edgehist: combo tables + BN1 + emb (independent of segsum).
    cudaStreamWaitEvent(sC, evH, 0);
    k_tables<<<NCOMBO + NTY, 256, 0, sC>>>(We1, be1);
    k_bnstat1p<<<DD, 128, 0, sC>>>();
    k_emb<<<NCOMBO + NTY, 256, 0, sC>>>(We2, be2, ge1, bte1);
    cudaEventRecord(evC, sC);

    // Main stream: segment sums (partials) + fixed-order reduction (deterministic).
    k_segsum3<<<NSEG, 128>>>(x);
    k_segred<<<(NT1 * DD + 255) / 256, 256>>>();

    // Join C (embE/embS ready), then rest of the table chain.
    cudaStreamWaitEvent(0, evC, 0);
    k_h2pre<<<NCOMBO, 256>>>(Wa1, ba1);
    k_bnstat2p<<<DD, 128>>>();
    k_Rtab<<<NCOMBO, 256>>>(Wa2, ba2, ga1, bta1);
    k_attn<<<BB, 256>>>(sent, Watt);
    k_ukum<<<BB + NTY, 256>>>(Wk, Wm);

    // Join A (XKMQ ready) before D1; join B (sorted CSR ready) before D2.
    cudaStreamWaitEvent(0, evA, 0);
    k_D1<<<(TOTROWS + 7) / 8, 256>>>(ei, ntp);
    cudaStreamWaitEvent(0, evB, 0);
    k_D2w<<<NN / 8, 256>>>(ei, ntp);
    {   // Y1 = aggr @ Wo1 + bo1  (+ fused fp64 column stats)
        dim3 g(2, NN / 128);
        k_gemmT<1><<<g, 256>>>(NN, DD, DD, pAggr, DD, pWo1P, 256, pY1, DD,
                               bo1, nullptr, nullptr, nullptr, nullptr);
    }
    k_stat3<<<1, 256>>>();
    {   // out = relu(bn(Y1)) @ Wo2 + bo2
        dim3 g(2, NN / 128);
        k_gemmT<0><<<g, 256>>>(NN, DD, DD, pY1, DD, pWo2P, 256, out, DD,
                               bo2, pb3m, pb3r, go1, bto1);
    }
}

// round 17
// speedup vs baseline: 1.0191x; 1.0055x over previous
#include <cuda_runtime.h>
#include <math.h>
#include <stdint.h>

#define DD 200
#define NTY 4
#define NET 38
#define NT1 39
#define BB 256
#define LL 1024
#define EE 262144
#define NN 51200
#define NCOMBO 608
#define TOTROWS (EE + NN)
#define NSEG 400

// f32x2 packed-math helpers
#define FMA2(d,a,b)  asm("fma.rn.f32x2 %0, %1, %2, %3;" : "=l"(d) : "l"(a), "l"(b), "l"(d))
#define PACK2(d,x,y) asm("mov.b64 %0, {%1, %2};" : "=l"(d) : "f"(x), "f"(y))
#define UNPACK2(x,y,d) asm("mov.b64 {%0, %1}, %2;" : "=f"(x), "=f"(y) : "l"(d))

#define CVT_TF32(u,f) asm("cvt.rna.tf32.f32 %0, %1;" : "=r"(u) : "f"(f))
#define MMA_TF32(c0,c1,c2,c3,a0,a1,a2,a3,b0,b1) \
  asm("mma.sync.aligned.m16n8k8.row.col.f32.tf32.tf32.f32 " \
      "{%0,%1,%2,%3},{%4,%5,%6,%7},{%8,%9},{%0,%1,%2,%3};" \
      : "+f"(c0),"+f"(c1),"+f"(c2),"+f"(c3) \
      : "r"(a0),"r"(a1),"r"(a2),"r"(a3),"r"(b0),"r"(b1))

// ------------------------- scratch -------------------------
__device__ float d_coeff[(size_t)NN * NT1];
__device__ float d_part[(size_t)NSEG * NT1 * DD];   // per-block segment-sum partials
__device__ int   d_cntT[NT1];
__device__ int   d_cntE[NCOMBO];
__device__ int   d_cntN[NTY];
__device__ int   d_combo[EE];
__device__ int   d_cntSrc[NN];
__device__ int   d_dstCnt[NN];
__device__ int   d_dstOff[NN + 1];
__device__ int   d_cursor[NN];
__device__ int   d_csr[TOTROWS];
__device__ int   d_blkSum[50];
__device__ float d_meanT[NT1 * DD];
__device__ float d_preE[NCOMBO * DD];
__device__ float d_preS[NTY * DD];
__device__ float d_embE[NCOMBO * DD];
__device__ float d_embS[NTY * DD];
__device__ float d_h2[NCOMBO * DD];
__device__ float d_Rtab[NCOMBO * DD];
__device__ float d_bn1m[DD], d_bn1r[DD], d_bn2m[DD], d_bn2r[DD], d_bn3m[DD], d_bn3r[DD];
__device__ float d_upd[BB * DD];
__device__ float d_UKall[(BB + NTY) * DD];
__device__ float d_UMall[(BB + NTY) * DD];
__device__ float d_Wcat[DD * 640];
__device__ float d_bcat[640];
__device__ float d_Wo1P[DD * 256];
__device__ float d_Wo2P[DD * 256];
__device__ float d_XKMQ[(size_t)NN * 600];    // per-node [XK+bk | XM+bm | (XQ+bq)*invs]
__device__ float d_ex[(size_t)TOTROWS * 4];
__device__ float d_den[NN * 4];
__device__ float d_aggr[(size_t)NN * DD];
__device__ float d_Y1[(size_t)NN * DD];
__device__ double d_colsum[DD], d_colsum2[DD];   // fp64 BN3 stats

// ------------------------- zero init + node hist (fused) -------------------------
__global__ void k_zero(const int* __restrict__ ntp) {
    long long i0 = (long long)blockIdx.x * blockDim.x + threadIdx.x;
    long long st = (long long)gridDim.x * blockDim.x;
    for (long long i = i0; i < (long long)NT1 * NN; i += st) d_coeff[i] = 0.f;
    for (long long i = i0; i < (long long)NN * 4; i += st) d_den[i] = 0.f;
    for (long long i = i0; i < NCOMBO; i += st) d_cntE[i] = 0;
    for (long long i = i0; i < NT1; i += st) d_cntT[i] = 0;
    for (long long i = i0; i < NTY; i += st) d_cntN[i] = 0;
    for (long long i = i0; i < DD; i += st) { d_colsum[i] = 0.0; d_colsum2[i] = 0.0; }
    for (long long i = i0; i < NN; i += st) {
        d_cntSrc[i] = 1;
        d_dstCnt[i] = 1;
        atomicAdd(&d_cntN[ntp[i]], 1);
    }
}

// smem histograms + 2 edges/thread (ILP) x 512 blocks (occupancy)
__global__ void k_edgehist(const int* __restrict__ ei, const int* __restrict__ et,
                           const int* __restrict__ ntp) {
    __shared__ int sT[NT1];
    __shared__ int sE[NCOMBO];
    int tid = threadIdx.x;
    for (int i = tid; i < NT1; i += 256) sT[i] = 0;
    for (int i = tid; i < NCOMBO; i += 256) sE[i] = 0;
    __syncthreads();
    int e0 = blockIdx.x * 512 + tid;
    int s[2], dd[2], t[2];
#pragma unroll
    for (int j = 0; j < 2; j++) {
        int e = e0 + j * 256;
        s[j]  = ei[e];
        dd[j] = ei[EE + e];
        t[j]  = et[e];
    }
#pragma unroll
    for (int j = 0; j < 2; j++)
        atomicAdd(&d_coeff[(size_t)dd[j] * NT1 + t[j]], 1.f);
#pragma unroll
    for (int j = 0; j < 2; j++)
        atomicAdd(&d_coeff[(size_t)s[j] * NT1 + t[j]], -1.f);
#pragma unroll
    for (int j = 0; j < 2; j++) {
        int e = e0 + j * 256;
        atomicAdd(&sT[t[j]], 1);
        int c = (t[j] << 4) | (ntp[s[j]] << 2) | ntp[dd[j]];
        d_combo[e] = c;
        atomicAdd(&sE[c], 1);
    }
#pragma unroll
    for (int j = 0; j < 2; j++) atomicAdd(&d_cntSrc[s[j]], 1);
#pragma unroll
    for (int j = 0; j < 2; j++) atomicAdd(&d_dstCnt[dd[j]], 1);
    __syncthreads();
    for (int i = tid; i < NT1; i += 256) if (sT[i]) atomicAdd(&d_cntT[i], sT[i]);
    for (int i = tid; i < NCOMBO; i += 256) if (sE[i]) atomicAdd(&d_cntE[i], sE[i]);
}

// ------------------------- dst-CSR build (3-phase parallel scan) -------------------------
__global__ void k_scanA() {
    __shared__ int sm[1024];
    int tid = threadIdx.x;
    sm[tid] = d_dstCnt[blockIdx.x * 1024 + tid];
    __syncthreads();
    for (int o = 512; o > 0; o >>= 1) {
        if (tid < o) sm[tid] += sm[tid + o];
        __syncthreads();
    }
    if (tid == 0) d_blkSum[blockIdx.x] = sm[0];
}

__global__ void k_scanB() {
    __shared__ int sm[64];
    int tid = threadIdx.x;
    int v = (tid < 50) ? d_blkSum[tid] : 0;
    sm[tid] = v;
    __syncthreads();
    for (int o = 1; o < 64; o <<= 1) {
        int t = (tid >= o) ? sm[tid - o] : 0;
        __syncthreads();
        sm[tid] += t;
        __syncthreads();
    }
    if (tid < 50) d_blkSum[tid] = sm[tid] - v;
    if (tid == 49) d_dstOff[NN] = sm[49];
}

__global__ void k_scanC() {
    __shared__ int sm[1024];
    int tid = threadIdx.x;
    int g = blockIdx.x * 1024 + tid;
    int v = d_dstCnt[g];
    sm[tid] = v;
    __syncthreads();
    for (int o = 1; o < 1024; o <<= 1) {
        int t = (tid >= o) ? sm[tid - o] : 0;
        __syncthreads();
        sm[tid] += t;
        __syncthreads();
    }
    int excl = sm[tid] - v + d_blkSum[blockIdx.x];
    d_dstOff[g] = excl;
    d_cursor[g] = excl;
}

__global__ void k_csrfill(const int* __restrict__ ei) {
    int i = blockIdx.x * blockDim.x + threadIdx.x;
    if (i >= TOTROWS) return;
    int dst = (i < EE) ? ei[EE + i] : (i - EE);
    int pos = atomicAdd(&d_cursor[dst], 1);
    d_csr[pos] = i;
}

// sort each node's CSR segment by edge index -> deterministic D2 accumulation order
__global__ void k_csrsort() {
    int n = blockIdx.x * blockDim.x + threadIdx.x;
    if (n >= NN) return;
    int beg = d_dstOff[n], end = d_dstOff[n + 1];
    for (int i = beg + 1; i < end; i++) {
        int v = d_csr[i];
        int j = i - 1;
        while (j >= beg && d_csr[j] > v) { d_csr[j + 1] = d_csr[j]; j--; }
        d_csr[j + 1] = v;
    }
}

// ------------------------- segment sums (deterministic: partials + fixed-order reduce) ----
__global__ __launch_bounds__(128) void k_segsum3(const float* __restrict__ x) {
    __shared__ unsigned long long cf2[128][NT1];
    int tid = threadIdx.x;
    int n0 = blockIdx.x * 128;
    for (int i = tid; i < 128 * NT1; i += 128) {
        float c = d_coeff[(size_t)(n0 + i / NT1) * NT1 + (i % NT1)];
        unsigned long long c2; PACK2(c2, c, c);
        cf2[i / NT1][i % NT1] = c2;
    }
    __syncthreads();
    if (tid < 100) {
        unsigned long long acc[NT1];
#pragma unroll
        for (int t = 0; t < NT1; t++) acc[t] = 0ULL;
        for (int nn = 0; nn < 128; nn++) {
            float2 xv = *(const float2*)&x[(size_t)(n0 + nn) * DD + tid * 2];
            unsigned long long xv2; PACK2(xv2, xv.x, xv.y);
#pragma unroll
            for (int t = 0; t < NT1; t++)
                FMA2(acc[t], cf2[nn][t], xv2);
        }
        float* dst = &d_part[(size_t)blockIdx.x * (NT1 * DD)];
#pragma unroll
        for (int t = 0; t < NT1; t++) {
            float lo, hi; UNPACK2(lo, hi, acc[t]);
            dst[t * DD + tid * 2]     = lo;
            dst[t * DD + tid * 2 + 1] = hi;
        }
    }
}

// fixed-order reduction over the 400 partials, fused with meanT
__global__ void k_segred() {
    int i = blockIdx.x * 256 + threadIdx.x;
    if (i >= NT1 * DD) return;
    float s = 0.f;
    for (int b = 0; b < NSEG; b++)
        s += d_part[(size_t)b * (NT1 * DD) + i];
    int t = i / DD;
    float c = (float)d_cntT[t];
    if (c < 1.f) c = 1.f;
    d_meanT[i] = s / c;
}

// ------------------------- combo tables -------------------------
__global__ void k_tables(const float* __restrict__ We1, const float* __restrict__ be1) {
    int c = blockIdx.x, d = threadIdx.x;
    if (d >= DD) return;
    if (c < NCOMBO) {
        int t = c >> 4, a = (c >> 2) & 3, b = c & 3;
        d_preE[c * DD + d] = We1[t * DD + d] + We1[(NT1 + a) * DD + d]
                           + We1[(NT1 + NTY + b) * DD + d] + be1[d];
    } else {
        int t = c - NCOMBO;
        d_preS[t * DD + d] = We1[NET * DD + d] + We1[(NT1 + t) * DD + d]
                           + We1[(NT1 + NTY + t) * DD + d] + be1[d];
    }
}

__global__ void k_bnstat1p() {
    int d = blockIdx.x, tid = threadIdx.x;
    __shared__ double rs[128], rs2[128];
    double s = 0.0, s2 = 0.0;
    for (int c = tid; c < NCOMBO; c += 128) {
        double w = (double)d_cntE[c], v = (double)d_preE[c * DD + d];
        s += w * v; s2 += w * v * v;
    }
    if (tid < NTY) {
        double w = (double)d_cntN[tid], v = (double)d_preS[tid * DD + d];
        s += w * v; s2 += w * v * v;
    }
    rs[tid] = s; rs2[tid] = s2;
    __syncthreads();
    for (int o = 64; o > 0; o >>= 1) {
        if (tid < o) { rs[tid] += rs[tid + o]; rs2[tid] += rs2[tid + o]; }
        __syncthreads();
    }
    if (tid == 0) {
        double m = rs[0] / (double)TOTROWS;
        double var = rs2[0] / (double)TOTROWS - m * m;
        d_bn1m[d] = (float)m;
        d_bn1r[d] = rsqrtf((float)var + 1e-5f);
    }
}

__global__ void k_emb(const float* __restrict__ We2, const float* __restrict__ be2,
                      const float* __restrict__ g, const float* __restrict__ bt) {
    int c = blockIdx.x, d = threadIdx.x;
    __shared__ float a[DD];
    const float* srow = (c < NCOMBO) ? &d_preE[c * DD] : &d_preS[(c - NCOMBO) * DD];
    if (d < DD) {
        float v = (srow[d] - d_bn1m[d]) * d_bn1r[d] * g[d] + bt[d];
        a[d] = fmaxf(v, 0.f);
    }
    __syncthreads();
    if (d < DD) {
        float acc = 0.f;
        for (int k = 0; k < DD; k++) acc += a[k] * We2[k * DD + d];
        float* dst = (c < NCOMBO) ? &d_embE[c * DD] : &d_embS[(c - NCOMBO) * DD];
        dst[d] = acc + be2[d];
    }
}

__global__ void k_h2pre(const float* __restrict__ Wa1, const float* __restrict__ ba1) {
    int c = blockIdx.x, d = threadIdx.x;
    __shared__ float e[DD], mt[DD];
    int t = c >> 4;
    if (d < DD) { e[d] = d_embE[c * DD + d]; mt[d] = d_meanT[t * DD + d]; }
    __syncthreads();
    if (d < DD) {
        float acc = ba1[d];
        for (int k = 0; k < DD; k++) acc += e[k] * Wa1[k * DD + d];
        for (int k = 0; k < DD; k++) acc += mt[k] * Wa1[(DD + k) * DD + d];
        d_h2[c * DD + d] = acc;
    }
}

__global__ void k_bnstat2p() {
    int d = blockIdx.x, tid = threadIdx.x;
    __shared__ double rs[128], rs2[128];
    double s = 0.0, s2 = 0.0;
    for (int c = tid; c < NCOMBO; c += 128) {
        double w = (double)d_cntE[c], v = (double)d_h2[c * DD + d];
        s += w * v; s2 += w * v * v;
    }
    rs[tid] = s; rs2[tid] = s2;
    __syncthreads();
    for (int o = 64; o > 0; o >>= 1) {
        if (tid < o) { rs[tid] += rs[tid + o]; rs2[tid] += rs2[tid + o]; }
        __syncthreads();
    }
    if (tid == 0) {
        double m = rs[0] / (double)EE;
        double var = rs2[0] / (double)EE - m * m;
        d_bn2m[d] = (float)m;
        d_bn2r[d] = rsqrtf((float)var + 1e-5f);
    }
}

__global__ void k_Rtab(const float* __restrict__ Wa2, const float* __restrict__ ba2,
                       const float* __restrict__ g, const float* __restrict__ bt) {
    int c = blockIdx.x, d = threadIdx.x;
    __shared__ float a[DD];
    if (d < DD) {
        float v = (d_h2[c * DD + d] - d_bn2m[d]) * d_bn2r[d] * g[d] + bt[d];
        a[d] = fmaxf(v, 0.f);
    }
    __syncthreads();
    if (d < DD) {
        float acc = 0.f;
        for (int k = 0; k < DD; k++) acc += a[k] * Wa2[k * DD + d];
        d_Rtab[c * DD + d] = acc + ba2[d];
    }
}

// ------------------------- fused graph attention -------------------------
__global__ __launch_bounds__(256) void k_attn(const float* __restrict__ sent,
                                              const float* __restrict__ Watt) {
    int b = blockIdx.x, tid = threadIdx.x;
    __shared__ float sv[DD], q[DD];
    __shared__ float Pb[NCOMBO], Wacc[NCOMBO];
    __shared__ float red[256];
    if (tid < DD) sv[tid] = sent[b * DD + tid];
    for (int i = tid; i < NCOMBO; i += 256) Wacc[i] = 0.f;
    __syncthreads();
    if (tid < DD) {
        float a = 0.f;
        for (int k = 0; k < DD; k++) a += sv[k] * Watt[k * DD + tid];
        q[tid] = a * 0.07071067811865475f;   // 1/sqrt(200)
    }
    __syncthreads();
    int lane = tid & 31, w = tid >> 5;
    for (int c = w; c < NCOMBO; c += 8) {
        float p = 0.f;
        for (int k = lane; k < DD; k += 32) p += q[k] * d_Rtab[c * DD + k];
        for (int o = 16; o > 0; o >>= 1) p += __shfl_down_sync(0xffffffffu, p, o);
        if (lane == 0) Pb[c] = p;
    }
    __syncthreads();
    int cid[4]; float sc[4]; float lmax = -1e30f;
#pragma unroll
    for (int j = 0; j < 4; j++) {
        int e = b * LL + tid + j * 256;
        cid[j] = d_combo[e];
        sc[j] = Pb[cid[j]];
        lmax = fmaxf(lmax, sc[j]);
    }
    red[tid] = lmax; __syncthreads();
    for (int s = 128; s > 0; s >>= 1) { if (tid < s) red[tid] = fmaxf(red[tid], red[tid + s]); __syncthreads(); }
    float bmax = red[0]; __syncthreads();
    float lsum = 0.f;
#pragma unroll
    for (int j = 0; j < 4; j++) { sc[j] = expf(sc[j] - bmax); lsum += sc[j]; }
    red[tid] = lsum; __syncthreads();
    for (int s = 128; s > 0; s >>= 1) { if (tid < s) red[tid] += red[tid + s]; __syncthreads(); }
    float inv = 1.f / red[0]; __syncthreads();
#pragma unroll
    for (int j = 0; j < 4; j++) atomicAdd(&Wacc[cid[j]], sc[j] * inv);
    __syncthreads();
    if (tid < DD) {
        float a = 0.f;
        for (int c = 0; c < NCOMBO; c++) a += Wacc[c] * d_Rtab[c * DD + tid];
        d_upd[b * DD + tid] = a;
    }
}

__global__ void k_ukum(const float* __restrict__ Wk, const float* __restrict__ Wm) {
    int id = blockIdx.x, d = threadIdx.x;
    __shared__ float s[DD];
    const float* srow = (id < BB) ? &d_upd[id * DD] : &d_embS[(id - BB) * DD];
    if (d < DD) s[d] = srow[d];
    __syncthreads();
    if (d < DD) {
        float ak = 0.f, am = 0.f;
        for (int k = 0; k < DD; k++) {
            float sv = s[k];
            ak += sv * Wk[(DD + k) * DD + d];
            am += sv * Wm[(DD + k) * DD + d];
        }
        d_UKall[id * DD + d] = ak;
        d_UMall[id * DD + d] = am;
    }
}

// ------------------------- weight packing -------------------------
__global__ void k_pack(const float* __restrict__ Wk, const float* __restrict__ Wm,
                       const float* __restrict__ Wq,
                       const float* __restrict__ bk, const float* __restrict__ bm,
                       const float* __restrict__ bq,
                       const float* __restrict__ Wo1, const float* __restrict__ Wo2) {
    const float invs = 0.1414213562373095f;   // 1/sqrt(50)
    int i = blockIdx.x * blockDim.x + threadIdx.x;
    if (i < DD * 640) {
        int k = i / 640, c = i % 640;
        float v = (c < DD) ? Wk[k * DD + c]
                : (c < 2 * DD) ? Wm[k * DD + (c - DD)]
                : (c < 3 * DD) ? Wq[k * DD + (c - 2 * DD)] * invs : 0.f;
        d_Wcat[i] = v;
        return;
    }
    int j = i - DD * 640;
    if (j < DD * 256) {
        int k = j >> 8, c = j & 255;
        d_Wo1P[j] = (c < DD) ? Wo1[k * DD + c] : 0.f;
        return;
    }
    j -= DD * 256;
    if (j < DD * 256) {
        int k = j >> 8, c = j & 255;
        d_Wo2P[j] = (c < DD) ? Wo2[k * DD + c] : 0.f;
        return;
    }
    j -= DD * 256;
    if (j < 640) {
        float v = (j < DD) ? bk[j]
                : (j < 2 * DD) ? bm[j - DD]
                : (j < 3 * DD) ? bq[j - 2 * DD] * invs : 0.f;
        d_bcat[j] = v;
    }
}

// ------------------------- tf32 GEMM: 128x128 tile, 2-stage smem pipeline -------------------------
template<int DOSTAT>
__global__ __launch_bounds__(256, 2) void k_gemmT(
    int M, int Nreal, int K,
    const float* __restrict__ A, int lda,
    const float* __restrict__ B, int ldb,
    float* __restrict__ C, int ldc,
    const float* __restrict__ bias,
    const float* __restrict__ bnm, const float* __restrict__ bnr,
    const float* __restrict__ bng, const float* __restrict__ bnb) {
    __shared__ uint32_t As[2][8][132];
    __shared__ uint32_t Bs[2][8][132];
    __shared__ double cs[128], cs2[128];
    int tid = threadIdx.x;
    int lane = tid & 31, warp = tid >> 5;
    int wm = warp >> 2, wn = warp & 3;
    int gid = lane >> 2, tg = lane & 3;
    int row0 = blockIdx.y * 128, col0 = blockIdx.x * 128;
    if (DOSTAT && tid < 128) { cs[tid] = 0.0; cs2[tid] = 0.0; }

    float acc[4][4][4];
#pragma unroll
    for (int mt = 0; mt < 4; mt++)
#pragma unroll
        for (int nt = 0; nt < 4; nt++)
#pragma unroll
            for (int r = 0; r < 4; r++) acc[mt][nt][r] = 0.f;

    int rowA = row0 + (tid >> 1);
    int kA = (tid & 1) * 4;
    int rowB = tid >> 5;
    int colB = (tid & 31) * 4;
    int m0 = wm * 64, n0 = wn * 32;
    int mrow = tid >> 1;
    int nk = K / 8;

    float4 av, bv;
    {
        av = *(const float4*)&A[(size_t)rowA * lda + kA];
        if (bnm) {
            int g = kA;
            av.x = fmaxf((av.x - bnm[g])     * bnr[g]     * bng[g]     + bnb[g],     0.f);
            av.y = fmaxf((av.y - bnm[g + 1]) * bnr[g + 1] * bng[g + 1] + bnb[g + 1], 0.f);
            av.z = fmaxf((av.z - bnm[g + 2]) * bnr[g + 2] * bng[g + 2] + bnb[g + 2], 0.f);
            av.w = fmaxf((av.w - bnm[g + 3]) * bnr[g + 3] * bng[g + 3] + bnb[g + 3], 0.f);
        }
        bv = *(const float4*)&B[(size_t)rowB * ldb + col0 + colB];
        uint32_t u0, u1, u2, u3;
        CVT_TF32(u0, av.x); CVT_TF32(u1, av.y); CVT_TF32(u2, av.z); CVT_TF32(u3, av.w);
        As[0][kA + 0][mrow] = u0; As[0][kA + 1][mrow] = u1;
        As[0][kA + 2][mrow] = u2; As[0][kA + 3][mrow] = u3;
        CVT_TF32(u0, bv.x); CVT_TF32(u1, bv.y); CVT_TF32(u2, bv.z); CVT_TF32(u3, bv.w);
        Bs[0][rowB][colB] = u0; Bs[0][rowB][colB + 1] = u1;
        Bs[0][rowB][colB + 2] = u2; Bs[0][rowB][colB + 3] = u3;
    }

    for (int kt = 0; kt < nk; kt++) {
        int cur = kt & 1;
        int nxt = cur ^ 1;
        bool has = (kt + 1 < nk);
        if (has) {
            int k0 = (kt + 1) * 8;
            av = *(const float4*)&A[(size_t)rowA * lda + k0 + kA];
            if (bnm) {
                int g = k0 + kA;
                av.x = fmaxf((av.x - bnm[g])     * bnr[g]     * bng[g]     + bnb[g],     0.f);
                av.y = fmaxf((av.y - bnm[g + 1]) * bnr[g + 1] * bng[g + 1] + bnb[g + 1], 0.f);
                av.z = fmaxf((av.z - bnm[g + 2]) * bnr[g + 2] * bng[g + 2] + bnb[g + 2], 0.f);
                av.w = fmaxf((av.w - bnm[g + 3]) * bnr[g + 3] * bng[g + 3] + bnb[g + 3], 0.f);
            }
            bv = *(const float4*)&B[(size_t)(k0 + rowB) * ldb + col0 + colB];
        }
        __syncthreads();
        if (has) {
            uint32_t u0, u1, u2, u3;
            CVT_TF32(u0, av.x); CVT_TF32(u1, av.y); CVT_TF32(u2, av.z); CVT_TF32(u3, av.w);
            As[nxt][kA + 0][mrow] = u0; As[nxt][kA + 1][mrow] = u1;
            As[nxt][kA + 2][mrow] = u2; As[nxt][kA + 3][mrow] = u3;
            CVT_TF32(u0, bv.x); CVT_TF32(u1, bv.y); CVT_TF32(u2, bv.z); CVT_TF32(u3, bv.w);
            Bs[nxt][rowB][colB] = u0; Bs[nxt][rowB][colB + 1] = u1;
            Bs[nxt][rowB][colB + 2] = u2; Bs[nxt][rowB][colB + 3] = u3;
        }
        uint32_t af[4][4], bf[4][2];
#pragma unroll
        for (int mt = 0; mt < 4; mt++) {
            int mb = m0 + mt * 16 + gid;
            af[mt][0] = As[cur][tg][mb];
            af[mt][1] = As[cur][tg][mb + 8];
            af[mt][2] = As[cur][tg + 4][mb];
            af[mt][3] = As[cur][tg + 4][mb + 8];
        }
#pragma unroll
        for (int nt = 0; nt < 4; nt++) {
            int nb = n0 + nt * 8 + gid;
            bf[nt][0] = Bs[cur][tg][nb];
            bf[nt][1] = Bs[cur][tg + 4][nb];
        }
#pragma unroll
        for (int mt = 0; mt < 4; mt++)
#pragma unroll
            for (int nt = 0; nt < 4; nt++)
                MMA_TF32(acc[mt][nt][0], acc[mt][nt][1], acc[mt][nt][2], acc[mt][nt][3],
                         af[mt][0], af[mt][1], af[mt][2], af[mt][3],
                         bf[nt][0], bf[nt][1]);
    }

    float colS[4][2], colS2[4][2];
#pragma unroll
    for (int nt = 0; nt < 4; nt++) { colS[nt][0] = colS[nt][1] = 0.f; colS2[nt][0] = colS2[nt][1] = 0.f; }
#pragma unroll
    for (int mt = 0; mt < 4; mt++) {
        int r = row0 + m0 + mt * 16 + gid;
#pragma unroll
        for (int nt = 0; nt < 4; nt++) {
            int c = col0 + n0 + nt * 8 + tg * 2;
            float b0 = (bias && c < Nreal)     ? bias[c]     : 0.f;
            float b1 = (bias && c + 1 < Nreal) ? bias[c + 1] : 0.f;
            float v0 = acc[mt][nt][0] + b0;
            float v1 = acc[mt][nt][1] + b1;
            float v2 = acc[mt][nt][2] + b0;
            float v3 = acc[mt][nt][3] + b1;
            float* cr0 = &C[(size_t)r * ldc];
            float* cr1 = &C[(size_t)(r + 8) * ldc];
            if (c < Nreal)     { cr0[c] = v0; cr1[c] = v2; }
            if (c + 1 < Nreal) { cr0[c + 1] = v1; cr1[c + 1] = v3; }
            if (DOSTAT) {
                colS[nt][0]  += v0 + v2;
                colS2[nt][0] += v0 * v0 + v2 * v2;
                colS[nt][1]  += v1 + v3;
                colS2[nt][1] += v1 * v1 + v3 * v3;
            }
        }
    }
    if (DOSTAT) {
#pragma unroll
        for (int nt = 0; nt < 4; nt++) {
#pragma unroll
            for (int p = 0; p < 2; p++) {
                float a = colS[nt][p], b = colS2[nt][p];
                for (int o = 16; o >= 4; o >>= 1) {
                    a += __shfl_down_sync(0xffffffffu, a, o);
                    b += __shfl_down_sync(0xffffffffu, b, o);
                }
                colS[nt][p] = a; colS2[nt][p] = b;
            }
        }
        __syncthreads();
        if (gid == 0) {
#pragma unroll
            for (int nt = 0; nt < 4; nt++) {
                int lc = n0 + nt * 8 + tg * 2;
                atomicAdd(&cs[lc],      (double)colS[nt][0]);
                atomicAdd(&cs2[lc],     (double)colS2[nt][0]);
                atomicAdd(&cs[lc + 1],  (double)colS[nt][1]);
                atomicAdd(&cs2[lc + 1], (double)colS2[nt][1]);
            }
        }
        __syncthreads();
        if (tid < 128) {
            int gc = col0 + tid;
            if (gc < Nreal) {
                atomicAdd(&d_colsum[gc],  cs[tid]);
                atomicAdd(&d_colsum2[gc], cs2[tid]);
            }
        }
    }
}

// ------------------------- edge attention: scores + softmax denominators -------------------------
__global__ void k_D1(const int* __restrict__ ei, const int* __restrict__ ntp) {
    int warp = (blockIdx.x * blockDim.x + threadIdx.x) >> 5;
    int lane = threadIdx.x & 31;
    if (warp >= TOTROWS) return;
    int i = warp;
    int s, dd, kidx;
    if (i < EE) { s = ei[i]; dd = ei[EE + i]; kidx = i >> 10; }
    else { int n = i - EE; s = n; dd = n; kidx = BB + ntp[n]; }
    const float* kadd = &d_UKall[kidx * DD];
    const float* qrow = &d_XKMQ[(size_t)s * 600 + 400];
    const float* krow = &d_XKMQ[(size_t)dd * 600];
    int h = lane >> 3, r = lane & 7;
    float p = 0.f;
#pragma unroll
    for (int j = 0; j < 4; j++) {
        int idx = r + 8 * j;
        if (idx < 25) {
            int d0 = h * 50 + idx * 2;
            float2 q2 = *(const float2*)(qrow + d0);
            float2 k2 = *(const float2*)(krow + d0);
            float2 a2 = *(const float2*)(kadd + d0);
            p += q2.x * (k2.x + a2.x) + q2.y * (k2.y + a2.y);
        }
    }
    p += __shfl_down_sync(0xffffffffu, p, 4);
    p += __shfl_down_sync(0xffffffffu, p, 2);
    p += __shfl_down_sync(0xffffffffu, p, 1);
    if (r == 0) {
        float exv = __expf(p);
        d_ex[(size_t)i * 4 + h] = exv;
        atomicAdd(&d_den[s * 4 + h], exv);
    }
}

// ------------------------- aggregation: one warp per dst node (sorted CSR => deterministic) ----
__global__ __launch_bounds__(256) void k_D2w(const int* __restrict__ ei,
                                             const int* __restrict__ ntp) {
    int gw = (blockIdx.x * blockDim.x + threadIdx.x) >> 5;
    int lane = threadIdx.x & 31;
    int w = threadIdx.x >> 5;
    if (gw >= NN) return;
    int n = gw;
    int beg = d_dstOff[n], end = d_dstOff[n + 1];
    __shared__ float s_al[8][16][4];
    __shared__ int s_j[8][16], s_u[8][16];
    float acc[7];
#pragma unroll
    for (int k = 0; k < 7; k++) acc[k] = 0.f;
    for (int base = beg; base < end; base += 16) {
        int cnt = min(16, end - base);
        if (lane < cnt) {
            int i = d_csr[base + lane];
            int s, j, u;
            if (i < EE) { s = ei[i]; j = s; u = i >> 10; }
            else { int nn2 = i - EE; s = nn2; j = nn2; u = BB + ntp[nn2]; }
            s_j[w][lane] = j;
            s_u[w][lane] = u;
            float csf = (float)d_cntSrc[s];
#pragma unroll
            for (int hh = 0; hh < 4; hh++)
                s_al[w][lane][hh] = __fdividef(d_ex[(size_t)i * 4 + hh], d_den[s * 4 + hh]) * csf;
        }
        __syncwarp();
        for (int r = 0; r < cnt; r++) {
            const float* mrow = &d_XKMQ[(size_t)s_j[w][r] * 600 + 200];
            const float* urow = &d_UMall[s_u[w][r] * DD];
            float a0 = s_al[w][r][0], a1 = s_al[w][r][1];
            float a2 = s_al[w][r][2], a3 = s_al[w][r][3];
#pragma unroll
            for (int k = 0; k < 7; k++) {
                int c = lane + 32 * k;
                if (c < DD) {
                    float al = c < 50 ? a0 : c < 100 ? a1 : c < 150 ? a2 : a3;
                    acc[k] += al * (mrow[c] + urow[c]);
                }
            }
        }
        __syncwarp();
    }
#pragma unroll
    for (int k = 0; k < 7; k++) {
        int c = lane + 32 * k;
        if (c < DD) d_aggr[(size_t)n * DD + c] = acc[k];
    }
}

__global__ void k_stat3() {
    int d = threadIdx.x;
    if (d >= DD) return;
    double m = d_colsum[d] / (double)NN;
    double var = d_colsum2[d] / (double)NN - m * m;
    d_bn3m[d] = (float)m;
    d_bn3r[d] = rsqrtf((float)var + 1e-5f);
}

// ------------------------- launch (forked graph: 4-way overlap) -------------------------
extern "C" void kernel_launch(void* const* d_in, const int* in_sizes, int n_in,
                              void* d_out, int out_size) {
    const float* x    = (const float*)d_in[0];
    const float* sent = (const float*)d_in[2];
    const float* We1  = (const float*)d_in[3];
    const float* be1  = (const float*)d_in[4];
    const float* ge1  = (const float*)d_in[5];
    const float* bte1 = (const float*)d_in[6];
    const float* We2  = (const float*)d_in[7];
    const float* be2  = (const float*)d_in[8];
    const float* Wa1  = (const float*)d_in[9];
    const float* ba1  = (const float*)d_in[10];
    const float* ga1  = (const float*)d_in[11];
    const float* bta1 = (const float*)d_in[12];
    const float* Wa2  = (const float*)d_in[13];
    const float* ba2  = (const float*)d_in[14];
    const float* Watt = (const float*)d_in[15];
    const float* Wk   = (const float*)d_in[16];
    const float* bk   = (const float*)d_in[17];
    const float* Wm   = (const float*)d_in[18];
    const float* bm   = (const float*)d_in[19];
    const float* Wq   = (const float*)d_in[20];
    const float* bq   = (const float*)d_in[21];
    const float* Wo1  = (const float*)d_in[22];
    const float* bo1  = (const float*)d_in[23];
    const float* go1  = (const float*)d_in[24];
    const float* bto1 = (const float*)d_in[25];
    const float* Wo2  = (const float*)d_in[26];
    const float* bo2  = (const float*)d_in[27];
    const int* ei     = (const int*)d_in[28];
    const int* et     = (const int*)d_in[29];
    const int* ntp    = (const int*)d_in[30];
    float* out = (float*)d_out;

    void* tmp;
    cudaGetSymbolAddress(&tmp, d_Wcat);  float* pWcat = (float*)tmp;
    cudaGetSymbolAddress(&tmp, d_bcat);  float* pbcat = (float*)tmp;
    cudaGetSymbolAddress(&tmp, d_Wo1P);  float* pWo1P = (float*)tmp;
    cudaGetSymbolAddress(&tmp, d_Wo2P);  float* pWo2P = (float*)tmp;
    cudaGetSymbolAddress(&tmp, d_XKMQ);  float* pXKMQ = (float*)tmp;
    cudaGetSymbolAddress(&tmp, d_aggr);  float* pAggr = (float*)tmp;
    cudaGetSymbolAddress(&tmp, d_Y1);    float* pY1   = (float*)tmp;
    cudaGetSymbolAddress(&tmp, d_bn3m);  float* pb3m  = (float*)tmp;
    cudaGetSymbolAddress(&tmp, d_bn3r);  float* pb3r  = (float*)tmp;

    static cudaStream_t sA = nullptr, sB = nullptr, sC = nullptr;
    static cudaEvent_t evStart = nullptr, evH = nullptr, evA = nullptr, evB = nullptr, evC = nullptr;
    if (!sA) {
        cudaStreamCreateWithFlags(&sA, cudaStreamNonBlocking);
        cudaStreamCreateWithFlags(&sB, cudaStreamNonBlocking);
        cudaStreamCreateWithFlags(&sC, cudaStreamNonBlocking);
        cudaEventCreateWithFlags(&evStart, cudaEventDisableTiming);
        cudaEventCreateWithFlags(&evH, cudaEventDisableTiming);
        cudaEventCreateWithFlags(&evA, cudaEventDisableTiming);
        cudaEventCreateWithFlags(&evB, cudaEventDisableTiming);
        cudaEventCreateWithFlags(&evC, cudaEventDisableTiming);
    }

    // Fork branch A at graph root: pack weights + big XKMQ GEMM (independent of everything else).
    cudaEventRecord(evStart, 0);
    cudaStreamWaitEvent(sA, evStart, 0);
    k_pack<<<(DD * 640 + 2 * DD * 256 + 640 + 255) / 256, 256, 0, sA>>>(Wk, Wm, Wq, bk, bm, bq, Wo1, Wo2);
    {   // XKMQ = x @ [Wk1|Wm1|Wq*invs] + [bk|bm|bq*invs]
        dim3 g(5, NN / 128);
        k_gemmT<0><<<g, 256, 0, sA>>>(NN, 600, DD, x, DD, pWcat, 640, pXKMQ, 600,
                                      pbcat, nullptr, nullptr, nullptr, nullptr);
    }
    cudaEventRecord(evA, sA);

    // Main stream: zero + edge histogram (2 edges/thread x 512 blocks).
    k_zero<<<1024, 256>>>(ntp);
    k_edgehist<<<EE / 512, 256>>>(ei, et, ntp);
    cudaEventRecord(evH, 0);

    // Fork branch B after edgehist: CSR build + deterministic segment sort.
    cudaStreamWaitEvent(sB, evH, 0);
    k_scanA<<<50, 1024, 0, sB>>>();
    k_scanB<<<1, 64, 0, sB>>>();
    k_scanC<<<50, 1024, 0, sB>>>();
    k_csrfill<<<(TOTROWS + 255) / 256, 256, 0, sB>>>(ei);
    k_csrsort<<<NN / 256, 256, 0, sB>>>();
    cudaEventRecord(evB, sB);

    // Fork branch C after edgehist: combo tables + BN1 + emb (independent of segsum).
    cudaStreamWaitEvent(sC, evH, 0);
    k_tables<<<NCOMBO + NTY, 256, 0, sC>>>(We1, be1);
    k_bnstat1p<<<DD, 128, 0, sC>>>();
    k_emb<<<NCOMBO + NTY, 256, 0, sC>>>(We2, be2, ge1, bte1);
    cudaEventRecord(evC, sC);

    // Main stream: segment sums (partials) + fixed-order reduction (deterministic).
    k_segsum3<<<NSEG, 128>>>(x);
    k_segred<<<(NT1 * DD + 255) / 256, 256>>>();

    // Join C (embE/embS ready), then rest of the table chain.
    cudaStreamWaitEvent(0, evC, 0);
    k_h2pre<<<NCOMBO, 256>>>(Wa1, ba1);
    k_bnstat2p<<<DD, 128>>>();
    k_Rtab<<<NCOMBO, 256>>>(Wa2, ba2, ga1, bta1);
    k_attn<<<BB, 256>>>(sent, Watt);
    k_ukum<<<BB + NTY, 256>>>(Wk, Wm);

    // Join A (XKMQ ready) before D1; join B (sorted CSR ready) before D2.
    cudaStreamWaitEvent(0, evA, 0);
    k_D1<<<(TOTROWS + 7) / 8, 256>>>(ei, ntp);
    cudaStreamWaitEvent(0, evB, 0);
    k_D2w<<<NN / 8, 256>>>(ei, ntp);
    {   // Y1 = aggr @ Wo1 + bo1  (+ fused fp64 column stats)
        dim3 g(2, NN / 128);
        k_gemmT<1><<<g, 256>>>(NN, DD, DD, pAggr, DD, pWo1P, 256, pY1, DD,
                               bo1, nullptr, nullptr, nullptr, nullptr);
    }
    k_stat3<<<1, 256>>>();
    {   // out = relu(bn(Y1)) @ Wo2 + bo2
        dim3 g(2, NN / 128);
        k_gemmT<0><<<g, 256>>>(NN, DD, DD, pY1, DD, pWo2P, 256, out, DD,
                               bo2, pb3m, pb3r, go1, bto1);
    }
}